// round 7
// baseline (speedup 1.0000x reference)
#include <cuda_runtime.h>
#include <math.h>

#define BATCH 8
#define NPTS  4096
#define DIM   512
#define KC    512
#define OUTD  10

// ---------------- scratch (static device globals; no allocs) ----------------
__device__ float g_buf0[(size_t)BATCH * NPTS * DIM];
__device__ float g_buf1[(size_t)BATCH * NPTS * DIM];
__device__ float g_centers[(size_t)BATCH * KC * DIM];
__device__ float g_x2[BATCH * NPTS];
__device__ float g_c2[BATCH * KC];
__device__ int g_labels[BATCH * NPTS];
__device__ int g_list[BATCH * NPTS];
__device__ int g_counts[BATCH * KC];
__device__ int g_offs[BATCH * KC];
__device__ float g_pooled[BATCH * DIM];

__device__ __forceinline__ float mishf(float x) {
    float sp = fmaxf(x, 0.0f) + log1pf(expf(-fabsf(x)));
    return x * tanhf(sp);
}

__device__ __forceinline__ void ffma2(unsigned long long& d, unsigned long long a,
                                      unsigned long long b) {
    asm("fma.rn.f32x2 %0, %1, %2, %0;" : "+l"(d) : "l"(a), "l"(b));
}
__device__ __forceinline__ unsigned long long dup2(unsigned x) {
    unsigned long long r;
    asm("mov.b64 %0, {%1, %1};" : "=l"(r) : "r"(x));
    return r;
}

// ---------------- fused: x2 for all rows; centers0 + c2 for first KC rows ---
__global__ void rowsq_init_kernel(const float* __restrict__ X) {
    int b = blockIdx.y, i = blockIdx.x, t = threadIdx.x;  // 128 threads
    const float* row = X + ((size_t)b * NPTS + i) * DIM;
    bool isC = (i < KC);
    float* crow = g_centers + ((size_t)b * KC + i) * DIM;
    float s = 0.f;
#pragma unroll
    for (int u = 0; u < 4; u++) {
        float v = row[t + 128 * u];
        if (isC) crow[t + 128 * u] = v;
        s += v * v;
    }
    for (int o = 16; o > 0; o >>= 1) s += __shfl_down_sync(0xffffffffu, s, o);
    __shared__ float w[4];
    if ((t & 31) == 0) w[t >> 5] = s;
    __syncthreads();
    if (t == 0) {
        float tot = w[0] + w[1] + w[2] + w[3];
        g_x2[b * NPTS + i] = tot;
        if (isC) g_c2[b * KC + i] = tot;
    }
}

// ============================================================================
// f32x2 GEMM core v4: 128x128 tile, BK=16 (halved barrier count), 128 threads,
// 16x8 micro-tile, internal loop over all N-tiles.
// MODE 0: assign -> writes argmin labels directly
// MODE 1: C = A@B (B is KxN) plain store
// MODE 2: pooled mish epilogue (bias + mish + column sum into g_pooled)
// ============================================================================
template <int MODE>
__global__ __launch_bounds__(128, 2) void gemm_kernel(
    const float* __restrict__ A, const float* __restrict__ B,
    float* __restrict__ C, const float* __restrict__ bias,
    int Kd, int Nn, size_t aBatch, size_t bBatch, size_t cBatch) {
    __shared__ __align__(16) float As[2][16][128];
    __shared__ __align__(16) float Bs[2][16][128];
    __shared__ unsigned long long skey[128];
    __shared__ float colsum[128];

    int b = blockIdx.z;
    const float* Ab = A + (size_t)b * aBatch;
    const float* Bb = B + (size_t)b * bBatch;
    int m0 = blockIdx.x * 128;
    int tid = threadIdx.x;
    int tx = tid & 15, ty = tid >> 4;

    // BK=16 loaders: row-per-thread for A / transposed-B (16 floats = 4xfloat4)
    int brow = tid >> 3, bq = (tid & 7) * 16;  // natural B (KxN): 16 rows, 8 thr/row

    float4 ra[4], rb[4];

    auto loadT = [&](int k0, int n0) {
#pragma unroll
        for (int q = 0; q < 4; q++)
            ra[q] = *(const float4*)(Ab + (size_t)(m0 + tid) * Kd + k0 + q * 4);
        if (MODE == 0) {
#pragma unroll
            for (int q = 0; q < 4; q++)
                rb[q] = *(const float4*)(Bb + (size_t)(n0 + tid) * Kd + k0 + q * 4);
        } else {
#pragma unroll
            for (int q = 0; q < 4; q++)
                rb[q] = *(const float4*)(Bb + (size_t)(k0 + brow) * Nn + n0 + bq + q * 4);
        }
    };
    auto storeT = [&](int s) {
#pragma unroll
        for (int q = 0; q < 4; q++)
#pragma unroll
            for (int j = 0; j < 4; j++) As[s][q * 4 + j][tid] = (&ra[q].x)[j];
        if (MODE == 0) {
#pragma unroll
            for (int q = 0; q < 4; q++)
#pragma unroll
                for (int j = 0; j < 4; j++) Bs[s][q * 4 + j][tid] = (&rb[q].x)[j];
        } else {
#pragma unroll
            for (int q = 0; q < 4; q++)
                *(float4*)&Bs[s][brow][bq + q * 4] = rb[q];
        }
    };

    if (MODE == 0) skey[tid] = 0xFFFFFFFFFFFFFFFFull;

    int nk = Kd >> 4;
    int ntiles = Nn >> 7;
    for (int nt = 0; nt < ntiles; nt++) {
        int n0 = nt << 7;
        unsigned long long acc[8][8];
#pragma unroll
        for (int i = 0; i < 8; i++)
#pragma unroll
            for (int j = 0; j < 8; j++) acc[i][j] = 0ull;

        loadT(0, n0);
        storeT(0);
        __syncthreads();

        int s = 0;
        for (int t = 0; t < nk; t++) {
            if (t + 1 < nk) loadT((t + 1) << 4, n0);
#pragma unroll
            for (int kk = 0; kk < 16; kk++) {
                const ulonglong2* apv = (const ulonglong2*)&As[s][kk][ty * 16];
                ulonglong2 A0 = apv[0], A1 = apv[1], A2 = apv[2], A3 = apv[3];
                uint4 b0 = *(const uint4*)&Bs[s][kk][tx * 8];
                uint4 b1 = *(const uint4*)&Bs[s][kk][tx * 8 + 4];
                unsigned long long ap[8] = {A0.x, A0.y, A1.x, A1.y,
                                            A2.x, A2.y, A3.x, A3.y};
                unsigned long long bd[8] = {dup2(b0.x), dup2(b0.y), dup2(b0.z),
                                            dup2(b0.w), dup2(b1.x), dup2(b1.y),
                                            dup2(b1.z), dup2(b1.w)};
#pragma unroll
                for (int i = 0; i < 8; i++)
#pragma unroll
                    for (int j = 0; j < 8; j++) ffma2(acc[i][j], ap[i], bd[j]);
            }
            if (t + 1 < nk) {
                storeT(s ^ 1);
                __syncthreads();
                s ^= 1;
            }
        }

        if (MODE == 0) {
            float c2v[8];
#pragma unroll
            for (int j = 0; j < 8; j++) c2v[j] = g_c2[b * KC + n0 + tx * 8 + j];
            float x2v[16];
#pragma unroll
            for (int i = 0; i < 16; i++)
                x2v[i] = g_x2[b * NPTS + m0 + ty * 16 + i];
#pragma unroll
            for (int mp = 0; mp < 8; mp++) {
#pragma unroll
                for (int h = 0; h < 2; h++) {
                    int rl = ty * 16 + 2 * mp + h;
                    unsigned long long best = 0xFFFFFFFFFFFFFFFFull;
#pragma unroll
                    for (int j = 0; j < 8; j++) {
                        float dot = ((const float*)&acc[mp][j])[h];
                        float d = (x2v[2 * mp + h] + c2v[j]) - 2.0f * dot;
                        unsigned u = __float_as_uint(d);
                        u = (u & 0x80000000u) ? ~u : (u | 0x80000000u);
                        unsigned long long key =
                            ((unsigned long long)u << 32) |
                            (unsigned)(n0 + tx * 8 + j);
                        best = (key < best) ? key : best;
                    }
                    atomicMin(&skey[rl], best);
                }
            }
        } else if (MODE == 1) {
            float* Cb = C + (size_t)b * cBatch;
#pragma unroll
            for (int mp = 0; mp < 8; mp++) {
#pragma unroll
                for (int h = 0; h < 2; h++) {
                    float* p = Cb + (size_t)(m0 + ty * 16 + 2 * mp + h) * Nn +
                               n0 + tx * 8;
                    float4 v0, v1;
#pragma unroll
                    for (int j = 0; j < 4; j++) {
                        (&v0.x)[j] = ((const float*)&acc[mp][j])[h];
                        (&v1.x)[j] = ((const float*)&acc[mp][j + 4])[h];
                    }
                    *(float4*)p = v0;
                    *(float4*)(p + 4) = v1;
                }
            }
        } else {
            colsum[tid] = 0.f;
            float bj[8];
#pragma unroll
            for (int j = 0; j < 8; j++) bj[j] = bias[n0 + tx * 8 + j];
            __syncthreads();
            float part[8] = {0, 0, 0, 0, 0, 0, 0, 0};
#pragma unroll
            for (int mp = 0; mp < 8; mp++)
#pragma unroll
                for (int j = 0; j < 8; j++) {
                    part[j] += mishf(((const float*)&acc[mp][j])[0] + bj[j]);
                    part[j] += mishf(((const float*)&acc[mp][j])[1] + bj[j]);
                }
#pragma unroll
            for (int j = 0; j < 8; j++) atomicAdd(&colsum[tx * 8 + j], part[j]);
            __syncthreads();
            atomicAdd(&g_pooled[b * DIM + n0 + tid], colsum[tid]);
        }
        __syncthreads();  // smem reuse + skey visibility for next tile / final
    }

    if (MODE == 0)
        g_labels[b * NPTS + m0 + tid] = (int)(skey[tid] & 0xFFFFFFFFu);
}

// ---------------- parallel stable member-list build (counting sort) ---------
__global__ __launch_bounds__(256) void listbuild_kernel() {
    __shared__ int labs[NPTS];     // 16KB
    __shared__ int cnt[8][KC];     // 16KB: counts -> chunk start cursors
    __shared__ int tot[KC];
    __shared__ int offs[KC];
    int b = blockIdx.x, t = threadIdx.x;
    int w = t >> 5, lane = t & 31;

    for (int idx = t; idx < 8 * KC; idx += 256) ((int*)cnt)[idx] = 0;
    for (int i = t; i < NPTS; i += 256) labs[i] = g_labels[b * NPTS + i];
    __syncthreads();

    for (int r = 0; r < 16; r++) {
        int i = w * 512 + r * 32 + lane;
        atomicAdd(&cnt[w][labs[i]], 1);
    }
    __syncthreads();

    for (int l = t; l < KC; l += 256) {
        int s = 0;
#pragma unroll
        for (int ch = 0; ch < 8; ch++) {
            int c = cnt[ch][l];
            cnt[ch][l] = s;
            s += c;
        }
        tot[l] = s;
    }
    __syncthreads();

    if (t < 32) {
        int carry = 0;
        for (int c = 0; c < KC / 32; c++) {
            int v = tot[c * 32 + t];
            int x = v;
#pragma unroll
            for (int o = 1; o < 32; o <<= 1) {
                int y = __shfl_up_sync(0xffffffffu, x, o);
                if (t >= o) x += y;
            }
            offs[c * 32 + t] = carry + x - v;
            carry += __shfl_sync(0xffffffffu, x, 31);
        }
    }
    __syncthreads();
    for (int l = t; l < KC; l += 256) {
        g_counts[b * KC + l] = tot[l];
        g_offs[b * KC + l] = offs[l];
    }
    for (int idx = t; idx < 8 * KC; idx += 256) {
        int ch = idx >> 9, l = idx & (KC - 1);
        cnt[ch][l] += offs[l];
    }
    __syncthreads();

    unsigned below = (lane == 0) ? 0u : (0xffffffffu >> (32 - lane));
    for (int r = 0; r < 16; r++) {
        int i = w * 512 + r * 32 + lane;
        int l = labs[i];
        unsigned mask = __match_any_sync(0xffffffffu, l);
        int base = cnt[w][l];
        __syncwarp();
        int rank = __popc(mask & below);
        g_list[b * NPTS + base + rank] = i;
        if (lane == __ffs(mask) - 1) cnt[w][l] = base + __popc(mask);
        __syncwarp();
    }
}

// ---------------- center update: gather listed members, 4-way ILP -----------
// Summation order per accumulator is IDENTICAL to the serial version
// (ascending list index); only load issue order changes -> bit-exact.
__global__ void gather_update_kernel(const float* __restrict__ X) {
    int b = blockIdx.y, k = blockIdx.x, t = threadIdx.x;  // 128 threads
    int cnt = g_counts[b * KC + k];
    int off = g_offs[b * KC + k];
    const int* lst = g_list + b * NPTS + off;
    const float* Xb = X + (size_t)b * NPTS * DIM;
    float a0 = 0, a1 = 0, a2 = 0, a3 = 0;
    int e = 0;
    for (; e + 4 <= cnt; e += 4) {
        int i0 = lst[e], i1 = lst[e + 1], i2 = lst[e + 2], i3 = lst[e + 3];
        const float* r0 = Xb + (size_t)i0 * DIM;
        const float* r1 = Xb + (size_t)i1 * DIM;
        const float* r2 = Xb + (size_t)i2 * DIM;
        const float* r3 = Xb + (size_t)i3 * DIM;
        float v00 = r0[t], v01 = r0[t + 128], v02 = r0[t + 256], v03 = r0[t + 384];
        float v10 = r1[t], v11 = r1[t + 128], v12 = r1[t + 256], v13 = r1[t + 384];
        float v20 = r2[t], v21 = r2[t + 128], v22 = r2[t + 256], v23 = r2[t + 384];
        float v30 = r3[t], v31 = r3[t + 128], v32 = r3[t + 256], v33 = r3[t + 384];
        a0 += v00; a1 += v01; a2 += v02; a3 += v03;
        a0 += v10; a1 += v11; a2 += v12; a3 += v13;
        a0 += v20; a1 += v21; a2 += v22; a3 += v23;
        a0 += v30; a1 += v31; a2 += v32; a3 += v33;
    }
    for (; e < cnt; e++) {
        const float* xr = Xb + (size_t)lst[e] * DIM;
        a0 += xr[t]; a1 += xr[t + 128]; a2 += xr[t + 256]; a3 += xr[t + 384];
    }
    float* crow = g_centers + ((size_t)b * KC + k) * DIM;
    float v0, v1, v2, v3;
    if (cnt > 0) {
        float cf = (float)cnt;
        v0 = a0 / cf; v1 = a1 / cf; v2 = a2 / cf; v3 = a3 / cf;
        crow[t] = v0; crow[t + 128] = v1; crow[t + 256] = v2; crow[t + 384] = v3;
    } else {
        v0 = crow[t]; v1 = crow[t + 128]; v2 = crow[t + 256]; v3 = crow[t + 384];
    }
    float sq = v0 * v0 + v1 * v1 + v2 * v2 + v3 * v3;
    for (int o = 16; o > 0; o >>= 1) sq += __shfl_down_sync(0xffffffffu, sq, o);
    __shared__ float w[4];
    if ((t & 31) == 0) w[t >> 5] = sq;
    __syncthreads();
    if (t == 0) g_c2[b * KC + k] = w[0] + w[1] + w[2] + w[3];
}

// ---------------- h_next = mish(adj @ one_hot(labels)), 16 rows/block -------
__global__ __launch_bounds__(256) void segsum_mish_kernel(const float* __restrict__ adj,
                                                          float* __restrict__ Hout) {
    int b = blockIdx.y, i0 = blockIdx.x * 16, t = threadIdx.x;  // 256 threads
    __shared__ float acc[16][KC];            // 32KB
    __shared__ unsigned short labs[NPTS];    // 8KB
    const int* lb = g_labels + b * NPTS;
    for (int j = t; j < NPTS; j += 256) labs[j] = (unsigned short)lb[j];
#pragma unroll
    for (int r = 0; r < 16; r++)
        for (int k = t; k < KC; k += 256) acc[r][k] = 0.f;
    __syncthreads();
#pragma unroll
    for (int r = 0; r < 16; r++) {
        const float* arow = adj + ((size_t)b * NPTS + i0 + r) * NPTS;
        for (int j = t; j < NPTS; j += 256) atomicAdd(&acc[r][labs[j]], arow[j]);
    }
    __syncthreads();
#pragma unroll
    for (int r = 0; r < 16; r++) {
        float* hrow = Hout + ((size_t)b * NPTS + i0 + r) * DIM;
        for (int k = t; k < KC; k += 256) hrow[k] = mishf(acc[r][k]);
    }
}

__global__ void zero_pooled_kernel() {
    g_pooled[blockIdx.x * DIM + threadIdx.x] = 0.f;
}

// ---------------- out = pooled @ Wp + bp ----------------
__global__ void out_kernel(const float* __restrict__ Wp, const float* __restrict__ bp,
                           float* __restrict__ out) {
    int b = blockIdx.x, t = threadIdx.x;  // 32 threads
    if (t < OUTD) {
        const float* p = g_pooled + b * DIM;
        float s = 0.f;
        for (int h = 0; h < DIM; h++) s += p[h] * Wp[h * OUTD + t];
        out[b * OUTD + t] = s + bp[t];
    }
}

// ---------------- host orchestration ----------------
static void run_ctod(const float* X, const float* centers) {
    rowsq_init_kernel<<<dim3(NPTS, BATCH), 128>>>(X);
    for (int it = 0; it < 10; it++) {
        gemm_kernel<0><<<dim3(NPTS / 128, 1, BATCH), 128>>>(
            X, centers, nullptr, nullptr, DIM, KC,
            (size_t)NPTS * DIM, (size_t)KC * DIM, (size_t)0);
        if (it < 9) {
            listbuild_kernel<<<BATCH, 256>>>();
            gather_update_kernel<<<dim3(KC, BATCH), 128>>>(X);
        }
    }
}

extern "C" void kernel_launch(void* const* d_in, const int* in_sizes, int n_in,
                              void* d_out, int out_size) {
    const float* x   = (const float*)d_in[0];
    const float* adj = (const float*)d_in[1];
    const float* W   = (const float*)d_in[2];
    const float* bb  = (const float*)d_in[3];
    const float* Wp  = (const float*)d_in[4];
    const float* bp  = (const float*)d_in[5];
    float* out = (float*)d_out;

    float *h0, *h1, *centers;
    cudaGetSymbolAddress((void**)&h0, g_buf0);
    cudaGetSymbolAddress((void**)&h1, g_buf1);
    cudaGetSymbolAddress((void**)&centers, g_centers);

    // Layer 1
    run_ctod(x, centers);
    segsum_mish_kernel<<<dim3(NPTS / 16, BATCH), 256>>>(adj, h0);
    // Layer 2
    run_ctod(h0, centers);
    segsum_mish_kernel<<<dim3(NPTS / 16, BATCH), 256>>>(adj, h1);
    // Layer 3
    run_ctod(h1, centers);
    segsum_mish_kernel<<<dim3(NPTS / 16, BATCH), 256>>>(adj, h0);

    // Final layer: t = h0 @ W, then pooled mish(adj @ t + b)
    gemm_kernel<1><<<dim3(NPTS / 128, 1, BATCH), 128>>>(
        h0, W, h1, nullptr, DIM, DIM,
        (size_t)NPTS * DIM, (size_t)0, (size_t)NPTS * DIM);
    zero_pooled_kernel<<<BATCH, DIM>>>();
    gemm_kernel<2><<<dim3(NPTS / 128, 1, BATCH), 128>>>(
        adj, h1, nullptr, bb, NPTS, DIM,
        (size_t)NPTS * NPTS, (size_t)NPTS * DIM, (size_t)0);
    out_kernel<<<BATCH, 32>>>(Wp, bp, out);
}

// round 9
// speedup vs baseline: 1.1160x; 1.1160x over previous
#include <cuda_runtime.h>
#include <math.h>

#define BATCH 8
#define NPTS  4096
#define DIM   512
#define KC    512
#define OUTD  10

// ---------------- scratch (static device globals; no allocs) ----------------
__device__ float g_buf0[(size_t)BATCH * NPTS * DIM];
__device__ float g_buf1[(size_t)BATCH * NPTS * DIM];
__device__ float g_centers[(size_t)BATCH * KC * DIM];
__device__ float g_x2[BATCH * NPTS];
__device__ float g_c2[BATCH * KC];
__device__ int g_labels[BATCH * NPTS];
__device__ int g_list[BATCH * NPTS];
__device__ int g_counts[BATCH * KC];
__device__ int g_offs[BATCH * KC];
__device__ float g_pooled[BATCH * DIM];

__device__ __forceinline__ float mishf(float x) {
    float sp = fmaxf(x, 0.0f) + log1pf(expf(-fabsf(x)));
    return x * tanhf(sp);
}

__device__ __forceinline__ void ffma2(unsigned long long& d, unsigned long long a,
                                      unsigned long long b) {
    asm("fma.rn.f32x2 %0, %1, %2, %0;" : "+l"(d) : "l"(a), "l"(b));
}
__device__ __forceinline__ unsigned long long dup2(unsigned x) {
    unsigned long long r;
    asm("mov.b64 %0, {%1, %1};" : "=l"(r) : "r"(x));
    return r;
}

// ---------------- fused: x2 for all rows; centers0 + c2 for first KC rows ---
__global__ void rowsq_init_kernel(const float* __restrict__ X) {
    int b = blockIdx.y, i = blockIdx.x, t = threadIdx.x;  // 128 threads
    const float* row = X + ((size_t)b * NPTS + i) * DIM;
    bool isC = (i < KC);
    float* crow = g_centers + ((size_t)b * KC + i) * DIM;
    float s = 0.f;
#pragma unroll
    for (int u = 0; u < 4; u++) {
        float v = row[t + 128 * u];
        if (isC) crow[t + 128 * u] = v;
        s += v * v;
    }
    for (int o = 16; o > 0; o >>= 1) s += __shfl_down_sync(0xffffffffu, s, o);
    __shared__ float w[4];
    if ((t & 31) == 0) w[t >> 5] = s;
    __syncthreads();
    if (t == 0) {
        float tot = w[0] + w[1] + w[2] + w[3];
        g_x2[b * NPTS + i] = tot;
        if (isC) g_c2[b * KC + i] = tot;
    }
}

// ============================================================================
// f32x2 GEMM core (R6-proven): 128x128 tile, BK=8, 128 threads, 16x8 microtile,
// internal loop over all N-tiles (grid = M-tiles x batch only).
// MODE 0: assign -> writes argmin labels directly
// MODE 1: C = A@B (B is KxN) plain store
// MODE 2: pooled mish epilogue (bias + mish + column sum into g_pooled)
// ============================================================================
template <int MODE>
__global__ __launch_bounds__(128, 2) void gemm_kernel(
    const float* __restrict__ A, const float* __restrict__ B,
    float* __restrict__ C, const float* __restrict__ bias,
    int Kd, int Nn, size_t aBatch, size_t bBatch, size_t cBatch) {
    __shared__ __align__(16) float As[2][8][128];
    __shared__ __align__(16) float Bs[2][8][128];
    __shared__ unsigned long long skey[128];
    __shared__ float colsum[128];

    int b = blockIdx.z;
    const float* Ab = A + (size_t)b * aBatch;
    const float* Bb = B + (size_t)b * bBatch;
    int m0 = blockIdx.x * 128;
    int tid = threadIdx.x;
    int tx = tid & 15, ty = tid >> 4;

    int ar = tid >> 1, akq = (tid & 1) * 4;   // A / transposed-B mapping
    int bkr = tid >> 5, bc4 = (tid & 31) * 4;  // natural B (KxN) mapping

    float4 ra0, ra1, rb0, rb1;

    auto loadT = [&](int k0, int n0) {
        ra0 = *(const float4*)(Ab + (size_t)(m0 + ar) * Kd + k0 + akq);
        ra1 = *(const float4*)(Ab + (size_t)(m0 + ar + 64) * Kd + k0 + akq);
        if (MODE == 0) {
            rb0 = *(const float4*)(Bb + (size_t)(n0 + ar) * Kd + k0 + akq);
            rb1 = *(const float4*)(Bb + (size_t)(n0 + ar + 64) * Kd + k0 + akq);
        } else {
            rb0 = *(const float4*)(Bb + (size_t)(k0 + bkr) * Nn + n0 + bc4);
            rb1 = *(const float4*)(Bb + (size_t)(k0 + bkr + 4) * Nn + n0 + bc4);
        }
    };
    auto storeT = [&](int s) {
#pragma unroll
        for (int j = 0; j < 4; j++) {
            As[s][akq + j][ar] = (&ra0.x)[j];
            As[s][akq + j][ar + 64] = (&ra1.x)[j];
        }
        if (MODE == 0) {
#pragma unroll
            for (int j = 0; j < 4; j++) {
                Bs[s][akq + j][ar] = (&rb0.x)[j];
                Bs[s][akq + j][ar + 64] = (&rb1.x)[j];
            }
        } else {
            *(float4*)&Bs[s][bkr][bc4] = rb0;
            *(float4*)&Bs[s][bkr + 4][bc4] = rb1;
        }
    };

    if (MODE == 0) skey[tid] = 0xFFFFFFFFFFFFFFFFull;

    int nk = Kd >> 3;
    int ntiles = Nn >> 7;
    for (int nt = 0; nt < ntiles; nt++) {
        int n0 = nt << 7;
        unsigned long long acc[8][8];
#pragma unroll
        for (int i = 0; i < 8; i++)
#pragma unroll
            for (int j = 0; j < 8; j++) acc[i][j] = 0ull;

        loadT(0, n0);
        storeT(0);
        __syncthreads();

        int s = 0;
        for (int t = 0; t < nk; t++) {
            if (t + 1 < nk) loadT((t + 1) << 3, n0);
#pragma unroll
            for (int kk = 0; kk < 8; kk++) {
                const ulonglong2* apv = (const ulonglong2*)&As[s][kk][ty * 16];
                ulonglong2 A0 = apv[0], A1 = apv[1], A2 = apv[2], A3 = apv[3];
                uint4 b0 = *(const uint4*)&Bs[s][kk][tx * 8];
                uint4 b1 = *(const uint4*)&Bs[s][kk][tx * 8 + 4];
                unsigned long long ap[8] = {A0.x, A0.y, A1.x, A1.y,
                                            A2.x, A2.y, A3.x, A3.y};
                unsigned long long bd[8] = {dup2(b0.x), dup2(b0.y), dup2(b0.z),
                                            dup2(b0.w), dup2(b1.x), dup2(b1.y),
                                            dup2(b1.z), dup2(b1.w)};
#pragma unroll
                for (int i = 0; i < 8; i++)
#pragma unroll
                    for (int j = 0; j < 8; j++) ffma2(acc[i][j], ap[i], bd[j]);
            }
            if (t + 1 < nk) {
                storeT(s ^ 1);
                __syncthreads();
                s ^= 1;
            }
        }

        if (MODE == 0) {
            float c2v[8];
#pragma unroll
            for (int j = 0; j < 8; j++) c2v[j] = g_c2[b * KC + n0 + tx * 8 + j];
            float x2v[16];
#pragma unroll
            for (int i = 0; i < 16; i++)
                x2v[i] = g_x2[b * NPTS + m0 + ty * 16 + i];
#pragma unroll
            for (int mp = 0; mp < 8; mp++) {
#pragma unroll
                for (int h = 0; h < 2; h++) {
                    int rl = ty * 16 + 2 * mp + h;
                    unsigned long long best = 0xFFFFFFFFFFFFFFFFull;
#pragma unroll
                    for (int j = 0; j < 8; j++) {
                        float dot = ((const float*)&acc[mp][j])[h];
                        float d = (x2v[2 * mp + h] + c2v[j]) - 2.0f * dot;
                        unsigned u = __float_as_uint(d);
                        u = (u & 0x80000000u) ? ~u : (u | 0x80000000u);
                        unsigned long long key =
                            ((unsigned long long)u << 32) |
                            (unsigned)(n0 + tx * 8 + j);
                        best = (key < best) ? key : best;
                    }
                    atomicMin(&skey[rl], best);
                }
            }
        } else if (MODE == 1) {
            float* Cb = C + (size_t)b * cBatch;
#pragma unroll
            for (int mp = 0; mp < 8; mp++) {
#pragma unroll
                for (int h = 0; h < 2; h++) {
                    float* p = Cb + (size_t)(m0 + ty * 16 + 2 * mp + h) * Nn +
                               n0 + tx * 8;
                    float4 v0, v1;
#pragma unroll
                    for (int j = 0; j < 4; j++) {
                        (&v0.x)[j] = ((const float*)&acc[mp][j])[h];
                        (&v1.x)[j] = ((const float*)&acc[mp][j + 4])[h];
                    }
                    *(float4*)p = v0;
                    *(float4*)(p + 4) = v1;
                }
            }
        } else {
            colsum[tid] = 0.f;
            float bj[8];
#pragma unroll
            for (int j = 0; j < 8; j++) bj[j] = bias[n0 + tx * 8 + j];
            __syncthreads();
            float part[8] = {0, 0, 0, 0, 0, 0, 0, 0};
#pragma unroll
            for (int mp = 0; mp < 8; mp++)
#pragma unroll
                for (int j = 0; j < 8; j++) {
                    part[j] += mishf(((const float*)&acc[mp][j])[0] + bj[j]);
                    part[j] += mishf(((const float*)&acc[mp][j])[1] + bj[j]);
                }
#pragma unroll
            for (int j = 0; j < 8; j++) atomicAdd(&colsum[tx * 8 + j], part[j]);
            __syncthreads();
            atomicAdd(&g_pooled[b * DIM + n0 + tid], colsum[tid]);
        }
        __syncthreads();  // smem reuse + skey visibility for next tile / final
    }

    if (MODE == 0)
        g_labels[b * NPTS + m0 + tid] = (int)(skey[tid] & 0xFFFFFFFFu);
}

// ---------------- parallel stable member-list build (counting sort) ---------
__global__ __launch_bounds__(256) void listbuild_kernel() {
    __shared__ int labs[NPTS];     // 16KB
    __shared__ int cnt[8][KC];     // 16KB: counts -> chunk start cursors
    __shared__ int tot[KC];
    __shared__ int offs[KC];
    int b = blockIdx.x, t = threadIdx.x;
    int w = t >> 5, lane = t & 31;

    for (int idx = t; idx < 8 * KC; idx += 256) ((int*)cnt)[idx] = 0;
    for (int i = t; i < NPTS; i += 256) labs[i] = g_labels[b * NPTS + i];
    __syncthreads();

    for (int r = 0; r < 16; r++) {
        int i = w * 512 + r * 32 + lane;
        atomicAdd(&cnt[w][labs[i]], 1);
    }
    __syncthreads();

    for (int l = t; l < KC; l += 256) {
        int s = 0;
#pragma unroll
        for (int ch = 0; ch < 8; ch++) {
            int c = cnt[ch][l];
            cnt[ch][l] = s;
            s += c;
        }
        tot[l] = s;
    }
    __syncthreads();

    if (t < 32) {
        int carry = 0;
        for (int c = 0; c < KC / 32; c++) {
            int v = tot[c * 32 + t];
            int x = v;
#pragma unroll
            for (int o = 1; o < 32; o <<= 1) {
                int y = __shfl_up_sync(0xffffffffu, x, o);
                if (t >= o) x += y;
            }
            offs[c * 32 + t] = carry + x - v;
            carry += __shfl_sync(0xffffffffu, x, 31);
        }
    }
    __syncthreads();
    for (int l = t; l < KC; l += 256) {
        g_counts[b * KC + l] = tot[l];
        g_offs[b * KC + l] = offs[l];
    }
    for (int idx = t; idx < 8 * KC; idx += 256) {
        int ch = idx >> 9, l = idx & (KC - 1);
        cnt[ch][l] += offs[l];
    }
    __syncthreads();

    unsigned below = (lane == 0) ? 0u : (0xffffffffu >> (32 - lane));
    for (int r = 0; r < 16; r++) {
        int i = w * 512 + r * 32 + lane;
        int l = labs[i];
        unsigned mask = __match_any_sync(0xffffffffu, l);
        int base = cnt[w][l];
        __syncwarp();
        int rank = __popc(mask & below);
        g_list[b * NPTS + base + rank] = i;
        if (lane == __ffs(mask) - 1) cnt[w][l] = base + __popc(mask);
        __syncwarp();
    }
}

// ---------------- center update: ONE WARP PER CLUSTER, lane owns 16 cols ----
// Per-column summation order = ascending member order (bit-exact vs serial).
// Each member contributes 4 independent LDG.128 per lane -> MLP=4, and
// ~28 warps/SM hide cluster-size imbalance.
__global__ __launch_bounds__(128) void gather_update_kernel(const float* __restrict__ X) {
    int b = blockIdx.y;
    int k = blockIdx.x * 4 + (threadIdx.x >> 5);  // 4 clusters per block
    int lane = threadIdx.x & 31;
    int cnt = g_counts[b * KC + k];
    int off = g_offs[b * KC + k];
    const int* lst = g_list + b * NPTS + off;
    const float* Xb = X + (size_t)b * NPTS * DIM;

    float4 a0 = {0, 0, 0, 0}, a1 = {0, 0, 0, 0}, a2 = {0, 0, 0, 0}, a3 = {0, 0, 0, 0};
    for (int e = 0; e < cnt; e++) {
        const float4* xr = (const float4*)(Xb + (size_t)lst[e] * DIM);
        float4 v0 = xr[lane], v1 = xr[lane + 32], v2 = xr[lane + 64], v3 = xr[lane + 96];
        a0.x += v0.x; a0.y += v0.y; a0.z += v0.z; a0.w += v0.w;
        a1.x += v1.x; a1.y += v1.y; a1.z += v1.z; a1.w += v1.w;
        a2.x += v2.x; a2.y += v2.y; a2.z += v2.z; a2.w += v2.w;
        a3.x += v3.x; a3.y += v3.y; a3.z += v3.z; a3.w += v3.w;
    }

    float4* crow = (float4*)(g_centers + ((size_t)b * KC + k) * DIM);
    float4 v0, v1, v2, v3;
    if (cnt > 0) {
        float cf = (float)cnt;
        v0 = make_float4(a0.x / cf, a0.y / cf, a0.z / cf, a0.w / cf);
        v1 = make_float4(a1.x / cf, a1.y / cf, a1.z / cf, a1.w / cf);
        v2 = make_float4(a2.x / cf, a2.y / cf, a2.z / cf, a2.w / cf);
        v3 = make_float4(a3.x / cf, a3.y / cf, a3.z / cf, a3.w / cf);
        crow[lane] = v0; crow[lane + 32] = v1; crow[lane + 64] = v2; crow[lane + 96] = v3;
    } else {
        v0 = crow[lane]; v1 = crow[lane + 32]; v2 = crow[lane + 64]; v3 = crow[lane + 96];
    }
    float sq = v0.x * v0.x + v0.y * v0.y + v0.z * v0.z + v0.w * v0.w
             + v1.x * v1.x + v1.y * v1.y + v1.z * v1.z + v1.w * v1.w
             + v2.x * v2.x + v2.y * v2.y + v2.z * v2.z + v2.w * v2.w
             + v3.x * v3.x + v3.y * v3.y + v3.z * v3.z + v3.w * v3.w;
    for (int o = 16; o > 0; o >>= 1) sq += __shfl_down_sync(0xffffffffu, sq, o);
    if (lane == 0) g_c2[b * KC + k] = sq;
}

// ---------------- h_next = mish(adj @ one_hot(labels)), 16 rows/block -------
__global__ __launch_bounds__(256) void segsum_mish_kernel(const float* __restrict__ adj,
                                                          float* __restrict__ Hout) {
    int b = blockIdx.y, i0 = blockIdx.x * 16, t = threadIdx.x;  // 256 threads
    __shared__ float acc[16][KC];            // 32KB
    __shared__ unsigned short labs[NPTS];    // 8KB
    const int* lb = g_labels + b * NPTS;
    for (int j = t; j < NPTS; j += 256) labs[j] = (unsigned short)lb[j];
#pragma unroll
    for (int r = 0; r < 16; r++)
        for (int k = t; k < KC; k += 256) acc[r][k] = 0.f;
    __syncthreads();
#pragma unroll
    for (int r = 0; r < 16; r++) {
        const float* arow = adj + ((size_t)b * NPTS + i0 + r) * NPTS;
        for (int j = t; j < NPTS; j += 256) atomicAdd(&acc[r][labs[j]], arow[j]);
    }
    __syncthreads();
#pragma unroll
    for (int r = 0; r < 16; r++) {
        float* hrow = Hout + ((size_t)b * NPTS + i0 + r) * DIM;
        for (int k = t; k < KC; k += 256) hrow[k] = mishf(acc[r][k]);
    }
}

__global__ void zero_pooled_kernel() {
    g_pooled[blockIdx.x * DIM + threadIdx.x] = 0.f;
}

// ---------------- out = pooled @ Wp + bp ----------------
__global__ void out_kernel(const float* __restrict__ Wp, const float* __restrict__ bp,
                           float* __restrict__ out) {
    int b = blockIdx.x, t = threadIdx.x;  // 32 threads
    if (t < OUTD) {
        const float* p = g_pooled + b * DIM;
        float s = 0.f;
        for (int h = 0; h < DIM; h++) s += p[h] * Wp[h * OUTD + t];
        out[b * OUTD + t] = s + bp[t];
    }
}

// ---------------- host orchestration ----------------
static void run_ctod(const float* X, const float* centers) {
    rowsq_init_kernel<<<dim3(NPTS, BATCH), 128>>>(X);
    for (int it = 0; it < 10; it++) {
        gemm_kernel<0><<<dim3(NPTS / 128, 1, BATCH), 128>>>(
            X, centers, nullptr, nullptr, DIM, KC,
            (size_t)NPTS * DIM, (size_t)KC * DIM, (size_t)0);
        if (it < 9) {
            listbuild_kernel<<<BATCH, 256>>>();
            gather_update_kernel<<<dim3(KC / 4, BATCH), 128>>>(X);
        }
    }
}

extern "C" void kernel_launch(void* const* d_in, const int* in_sizes, int n_in,
                              void* d_out, int out_size) {
    const float* x   = (const float*)d_in[0];
    const float* adj = (const float*)d_in[1];
    const float* W   = (const float*)d_in[2];
    const float* bb  = (const float*)d_in[3];
    const float* Wp  = (const float*)d_in[4];
    const float* bp  = (const float*)d_in[5];
    float* out = (float*)d_out;

    float *h0, *h1, *centers;
    cudaGetSymbolAddress((void**)&h0, g_buf0);
    cudaGetSymbolAddress((void**)&h1, g_buf1);
    cudaGetSymbolAddress((void**)&centers, g_centers);

    // Layer 1
    run_ctod(x, centers);
    segsum_mish_kernel<<<dim3(NPTS / 16, BATCH), 256>>>(adj, h0);
    // Layer 2
    run_ctod(h0, centers);
    segsum_mish_kernel<<<dim3(NPTS / 16, BATCH), 256>>>(adj, h1);
    // Layer 3
    run_ctod(h1, centers);
    segsum_mish_kernel<<<dim3(NPTS / 16, BATCH), 256>>>(adj, h0);

    // Final layer: t = h0 @ W, then pooled mish(adj @ t + b)
    gemm_kernel<1><<<dim3(NPTS / 128, 1, BATCH), 128>>>(
        h0, W, h1, nullptr, DIM, DIM,
        (size_t)NPTS * DIM, (size_t)0, (size_t)NPTS * DIM);
    zero_pooled_kernel<<<BATCH, DIM>>>();
    gemm_kernel<2><<<dim3(NPTS / 128, 1, BATCH), 128>>>(
        adj, h1, nullptr, bb, NPTS, DIM,
        (size_t)NPTS * NPTS, (size_t)NPTS * DIM, (size_t)0);
    out_kernel<<<BATCH, 32>>>(Wp, bp, out);
}

// round 10
// speedup vs baseline: 1.1979x; 1.0734x over previous
#include <cuda_runtime.h>
#include <math.h>

#define BATCH 8
#define NPTS  4096
#define DIM   512
#define KC    512
#define OUTD  10
#define NSLOT 768   // max 16-member chunks per batch: 4096/16 + 512 = 768

// ---------------- scratch (static device globals; no allocs) ----------------
__device__ float g_buf0[(size_t)BATCH * NPTS * DIM];
__device__ float g_buf1[(size_t)BATCH * NPTS * DIM];
__device__ float g_centers[(size_t)BATCH * KC * DIM];
__device__ float g_x2[BATCH * NPTS];
__device__ float g_c2[BATCH * KC];
__device__ int g_labels[BATCH * NPTS];
__device__ int g_list[BATCH * NPTS];
__device__ int g_counts[BATCH * KC];
__device__ int g_offs[BATCH * KC];
__device__ int g_choff[BATCH * KC];
__device__ int g_slot_s[BATCH * NSLOT];
__device__ int g_slot_n[BATCH * NSLOT];
__device__ int g_nslots[BATCH];
__device__ float g_partial[(size_t)BATCH * NSLOT * DIM];
__device__ float g_pooled[BATCH * DIM];

__device__ __forceinline__ float mishf(float x) {
    float sp = fmaxf(x, 0.0f) + log1pf(expf(-fabsf(x)));
    return x * tanhf(sp);
}

__device__ __forceinline__ void ffma2(unsigned long long& d, unsigned long long a,
                                      unsigned long long b) {
    asm("fma.rn.f32x2 %0, %1, %2, %0;" : "+l"(d) : "l"(a), "l"(b));
}
__device__ __forceinline__ unsigned long long dup2(unsigned x) {
    unsigned long long r;
    asm("mov.b64 %0, {%1, %1};" : "=l"(r) : "r"(x));
    return r;
}

// ---------------- fused: x2 for all rows; centers0 + c2 for first KC rows ---
__global__ void rowsq_init_kernel(const float* __restrict__ X) {
    int b = blockIdx.y, i = blockIdx.x, t = threadIdx.x;  // 128 threads
    const float* row = X + ((size_t)b * NPTS + i) * DIM;
    bool isC = (i < KC);
    float* crow = g_centers + ((size_t)b * KC + i) * DIM;
    float s = 0.f;
#pragma unroll
    for (int u = 0; u < 4; u++) {
        float v = row[t + 128 * u];
        if (isC) crow[t + 128 * u] = v;
        s += v * v;
    }
    for (int o = 16; o > 0; o >>= 1) s += __shfl_down_sync(0xffffffffu, s, o);
    __shared__ float w[4];
    if ((t & 31) == 0) w[t >> 5] = s;
    __syncthreads();
    if (t == 0) {
        float tot = w[0] + w[1] + w[2] + w[3];
        g_x2[b * NPTS + i] = tot;
        if (isC) g_c2[b * KC + i] = tot;
    }
}

// ============================================================================
// f32x2 GEMM core (proven): 128x128 tile, BK=8, 128 threads, 16x8 microtile,
// internal loop over all N-tiles (grid = M-tiles x batch only).
// MODE 0: assign -> writes argmin labels directly
// MODE 1: C = A@B (B is KxN) plain store
// MODE 2: pooled mish epilogue (bias + mish + column sum into g_pooled)
// ============================================================================
template <int MODE>
__global__ __launch_bounds__(128, 2) void gemm_kernel(
    const float* __restrict__ A, const float* __restrict__ B,
    float* __restrict__ C, const float* __restrict__ bias,
    int Kd, int Nn, size_t aBatch, size_t bBatch, size_t cBatch) {
    __shared__ __align__(16) float As[2][8][128];
    __shared__ __align__(16) float Bs[2][8][128];
    __shared__ unsigned long long skey[128];
    __shared__ float colsum[128];

    int b = blockIdx.z;
    const float* Ab = A + (size_t)b * aBatch;
    const float* Bb = B + (size_t)b * bBatch;
    int m0 = blockIdx.x * 128;
    int tid = threadIdx.x;
    int tx = tid & 15, ty = tid >> 4;

    int ar = tid >> 1, akq = (tid & 1) * 4;   // A / transposed-B mapping
    int bkr = tid >> 5, bc4 = (tid & 31) * 4;  // natural B (KxN) mapping

    float4 ra0, ra1, rb0, rb1;

    auto loadT = [&](int k0, int n0) {
        ra0 = *(const float4*)(Ab + (size_t)(m0 + ar) * Kd + k0 + akq);
        ra1 = *(const float4*)(Ab + (size_t)(m0 + ar + 64) * Kd + k0 + akq);
        if (MODE == 0) {
            rb0 = *(const float4*)(Bb + (size_t)(n0 + ar) * Kd + k0 + akq);
            rb1 = *(const float4*)(Bb + (size_t)(n0 + ar + 64) * Kd + k0 + akq);
        } else {
            rb0 = *(const float4*)(Bb + (size_t)(k0 + bkr) * Nn + n0 + bc4);
            rb1 = *(const float4*)(Bb + (size_t)(k0 + bkr + 4) * Nn + n0 + bc4);
        }
    };
    auto storeT = [&](int s) {
#pragma unroll
        for (int j = 0; j < 4; j++) {
            As[s][akq + j][ar] = (&ra0.x)[j];
            As[s][akq + j][ar + 64] = (&ra1.x)[j];
        }
        if (MODE == 0) {
#pragma unroll
            for (int j = 0; j < 4; j++) {
                Bs[s][akq + j][ar] = (&rb0.x)[j];
                Bs[s][akq + j][ar + 64] = (&rb1.x)[j];
            }
        } else {
            *(float4*)&Bs[s][bkr][bc4] = rb0;
            *(float4*)&Bs[s][bkr + 4][bc4] = rb1;
        }
    };

    if (MODE == 0) skey[tid] = 0xFFFFFFFFFFFFFFFFull;

    int nk = Kd >> 3;
    int ntiles = Nn >> 7;
    for (int nt = 0; nt < ntiles; nt++) {
        int n0 = nt << 7;
        unsigned long long acc[8][8];
#pragma unroll
        for (int i = 0; i < 8; i++)
#pragma unroll
            for (int j = 0; j < 8; j++) acc[i][j] = 0ull;

        loadT(0, n0);
        storeT(0);
        __syncthreads();

        int s = 0;
        for (int t = 0; t < nk; t++) {
            if (t + 1 < nk) loadT((t + 1) << 3, n0);
#pragma unroll
            for (int kk = 0; kk < 8; kk++) {
                const ulonglong2* apv = (const ulonglong2*)&As[s][kk][ty * 16];
                ulonglong2 A0 = apv[0], A1 = apv[1], A2 = apv[2], A3 = apv[3];
                uint4 b0 = *(const uint4*)&Bs[s][kk][tx * 8];
                uint4 b1 = *(const uint4*)&Bs[s][kk][tx * 8 + 4];
                unsigned long long ap[8] = {A0.x, A0.y, A1.x, A1.y,
                                            A2.x, A2.y, A3.x, A3.y};
                unsigned long long bd[8] = {dup2(b0.x), dup2(b0.y), dup2(b0.z),
                                            dup2(b0.w), dup2(b1.x), dup2(b1.y),
                                            dup2(b1.z), dup2(b1.w)};
#pragma unroll
                for (int i = 0; i < 8; i++)
#pragma unroll
                    for (int j = 0; j < 8; j++) ffma2(acc[i][j], ap[i], bd[j]);
            }
            if (t + 1 < nk) {
                storeT(s ^ 1);
                __syncthreads();
                s ^= 1;
            }
        }

        if (MODE == 0) {
            float c2v[8];
#pragma unroll
            for (int j = 0; j < 8; j++) c2v[j] = g_c2[b * KC + n0 + tx * 8 + j];
            float x2v[16];
#pragma unroll
            for (int i = 0; i < 16; i++)
                x2v[i] = g_x2[b * NPTS + m0 + ty * 16 + i];
#pragma unroll
            for (int mp = 0; mp < 8; mp++) {
#pragma unroll
                for (int h = 0; h < 2; h++) {
                    int rl = ty * 16 + 2 * mp + h;
                    unsigned long long best = 0xFFFFFFFFFFFFFFFFull;
#pragma unroll
                    for (int j = 0; j < 8; j++) {
                        float dot = ((const float*)&acc[mp][j])[h];
                        float d = (x2v[2 * mp + h] + c2v[j]) - 2.0f * dot;
                        unsigned u = __float_as_uint(d);
                        u = (u & 0x80000000u) ? ~u : (u | 0x80000000u);
                        unsigned long long key =
                            ((unsigned long long)u << 32) |
                            (unsigned)(n0 + tx * 8 + j);
                        best = (key < best) ? key : best;
                    }
                    atomicMin(&skey[rl], best);
                }
            }
        } else if (MODE == 1) {
            float* Cb = C + (size_t)b * cBatch;
#pragma unroll
            for (int mp = 0; mp < 8; mp++) {
#pragma unroll
                for (int h = 0; h < 2; h++) {
                    float* p = Cb + (size_t)(m0 + ty * 16 + 2 * mp + h) * Nn +
                               n0 + tx * 8;
                    float4 v0, v1;
#pragma unroll
                    for (int j = 0; j < 4; j++) {
                        (&v0.x)[j] = ((const float*)&acc[mp][j])[h];
                        (&v1.x)[j] = ((const float*)&acc[mp][j + 4])[h];
                    }
                    *(float4*)p = v0;
                    *(float4*)(p + 4) = v1;
                }
            }
        } else {
            colsum[tid] = 0.f;
            float bj[8];
#pragma unroll
            for (int j = 0; j < 8; j++) bj[j] = bias[n0 + tx * 8 + j];
            __syncthreads();
            float part[8] = {0, 0, 0, 0, 0, 0, 0, 0};
#pragma unroll
            for (int mp = 0; mp < 8; mp++)
#pragma unroll
                for (int j = 0; j < 8; j++) {
                    part[j] += mishf(((const float*)&acc[mp][j])[0] + bj[j]);
                    part[j] += mishf(((const float*)&acc[mp][j])[1] + bj[j]);
                }
#pragma unroll
            for (int j = 0; j < 8; j++) atomicAdd(&colsum[tx * 8 + j], part[j]);
            __syncthreads();
            atomicAdd(&g_pooled[b * DIM + n0 + tid], colsum[tid]);
        }
        __syncthreads();  // smem reuse + skey visibility for next tile / final
    }

    if (MODE == 0)
        g_labels[b * NPTS + m0 + tid] = (int)(skey[tid] & 0xFFFFFFFFu);
}

// ---------------- parallel stable member-list build + chunk slots -----------
__global__ __launch_bounds__(256) void listbuild_kernel() {
    __shared__ int labs[NPTS];     // 16KB
    __shared__ int cnt[8][KC];     // 16KB: counts -> chunk start cursors
    __shared__ int tot[KC];
    __shared__ int offs[KC];
    __shared__ int schoff[KC];
    int b = blockIdx.x, t = threadIdx.x;
    int w = t >> 5, lane = t & 31;

    for (int idx = t; idx < 8 * KC; idx += 256) ((int*)cnt)[idx] = 0;
    for (int i = t; i < NPTS; i += 256) labs[i] = g_labels[b * NPTS + i];
    __syncthreads();

    for (int r = 0; r < 16; r++) {
        int i = w * 512 + r * 32 + lane;
        atomicAdd(&cnt[w][labs[i]], 1);
    }
    __syncthreads();

    for (int l = t; l < KC; l += 256) {
        int s = 0;
#pragma unroll
        for (int ch = 0; ch < 8; ch++) {
            int c = cnt[ch][l];
            cnt[ch][l] = s;
            s += c;
        }
        tot[l] = s;
    }
    __syncthreads();

    // warp 0: exclusive scan of member counts; warp 1: scan of chunk counts
    if (t < 32) {
        int carry = 0;
        for (int c = 0; c < KC / 32; c++) {
            int v = tot[c * 32 + t];
            int x = v;
#pragma unroll
            for (int o = 1; o < 32; o <<= 1) {
                int y = __shfl_up_sync(0xffffffffu, x, o);
                if (t >= o) x += y;
            }
            offs[c * 32 + t] = carry + x - v;
            carry += __shfl_sync(0xffffffffu, x, 31);
        }
    } else if (t < 64) {
        int tl = t - 32;
        int carry = 0;
        for (int c = 0; c < KC / 32; c++) {
            int v = (tot[c * 32 + tl] + 15) >> 4;
            int x = v;
#pragma unroll
            for (int o = 1; o < 32; o <<= 1) {
                int y = __shfl_up_sync(0xffffffffu, x, o);
                if (tl >= o) x += y;
            }
            schoff[c * 32 + tl] = carry + x - v;
            carry += __shfl_sync(0xffffffffu, x, 31);
        }
        if (tl == 31) g_nslots[b] = carry;
    }
    __syncthreads();
    for (int l = t; l < KC; l += 256) {
        g_counts[b * KC + l] = tot[l];
        g_offs[b * KC + l] = offs[l];
        g_choff[b * KC + l] = schoff[l];
        // emit chunk slots for this cluster
        int nc = (tot[l] + 15) >> 4;
        int base = schoff[l];
        for (int j = 0; j < nc; j++) {
            g_slot_s[b * NSLOT + base + j] = offs[l] + j * 16;
            g_slot_n[b * NSLOT + base + j] = min(16, tot[l] - j * 16);
        }
    }
    for (int idx = t; idx < 8 * KC; idx += 256) {
        int ch = idx >> 9, l = idx & (KC - 1);
        cnt[ch][l] += offs[l];
    }
    __syncthreads();

    unsigned below = (lane == 0) ? 0u : (0xffffffffu >> (32 - lane));
    for (int r = 0; r < 16; r++) {
        int i = w * 512 + r * 32 + lane;
        int l = labs[i];
        unsigned mask = __match_any_sync(0xffffffffu, l);
        int base = cnt[w][l];
        __syncwarp();
        int rank = __popc(mask & below);
        g_list[b * NPTS + base + rank] = i;
        if (lane == __ffs(mask) - 1) cnt[w][l] = base + __popc(mask);
        __syncwarp();
    }
}

// ---------------- center update pass 1: sum each 16-member chunk ------------
// Deterministic: ascending member order within chunk. Chain depth <= 16.
__global__ __launch_bounds__(128) void gather_pass1_kernel(const float* __restrict__ X) {
    int b = blockIdx.y, slot = blockIdx.x, t = threadIdx.x;
    if (slot >= g_nslots[b]) return;
    int s = g_slot_s[b * NSLOT + slot];
    int n = g_slot_n[b * NSLOT + slot];
    const int* lst = g_list + b * NPTS + s;
    const float* Xb = X + (size_t)b * NPTS * DIM;
    float4 a = {0, 0, 0, 0};
    for (int e = 0; e < n; e++) {
        float4 v = *(const float4*)(Xb + (size_t)lst[e] * DIM + t * 4);
        a.x += v.x; a.y += v.y; a.z += v.z; a.w += v.w;
    }
    *(float4*)(g_partial + ((size_t)b * NSLOT + slot) * DIM + t * 4) = a;
}

// ---------------- center update pass 2: combine chunks, divide, c2 ----------
__global__ __launch_bounds__(128) void gather_pass2_kernel() {
    int b = blockIdx.y, k = blockIdx.x, t = threadIdx.x;
    int cnt = g_counts[b * KC + k];
    int c0 = g_choff[b * KC + k];
    int nch = (cnt + 15) >> 4;
    float* crow = g_centers + ((size_t)b * KC + k) * DIM;
    float4 v;
    if (cnt > 0) {
        float4 a = {0, 0, 0, 0};
        for (int c = 0; c < nch; c++) {
            float4 p = *(const float4*)(g_partial + ((size_t)b * NSLOT + c0 + c) * DIM + t * 4);
            a.x += p.x; a.y += p.y; a.z += p.z; a.w += p.w;
        }
        float cf = (float)cnt;
        v = make_float4(a.x / cf, a.y / cf, a.z / cf, a.w / cf);
        *(float4*)(crow + t * 4) = v;
    } else {
        v = *(const float4*)(crow + t * 4);
    }
    float sq = v.x * v.x + v.y * v.y + v.z * v.z + v.w * v.w;
    for (int o = 16; o > 0; o >>= 1) sq += __shfl_down_sync(0xffffffffu, sq, o);
    __shared__ float w[4];
    if ((t & 31) == 0) w[t >> 5] = sq;
    __syncthreads();
    if (t == 0) g_c2[b * KC + k] = w[0] + w[1] + w[2] + w[3];
}

// ---------------- h_next = mish(adj @ one_hot(labels)), 16 rows/block -------
__global__ __launch_bounds__(256) void segsum_mish_kernel(const float* __restrict__ adj,
                                                          float* __restrict__ Hout) {
    int b = blockIdx.y, i0 = blockIdx.x * 16, t = threadIdx.x;  // 256 threads
    __shared__ float acc[16][KC];            // 32KB
    __shared__ unsigned short labs[NPTS];    // 8KB
    const int* lb = g_labels + b * NPTS;
    for (int j = t; j < NPTS; j += 256) labs[j] = (unsigned short)lb[j];
#pragma unroll
    for (int r = 0; r < 16; r++)
        for (int k = t; k < KC; k += 256) acc[r][k] = 0.f;
    __syncthreads();
#pragma unroll
    for (int r = 0; r < 16; r++) {
        const float* arow = adj + ((size_t)b * NPTS + i0 + r) * NPTS;
        for (int j = t; j < NPTS; j += 256) atomicAdd(&acc[r][labs[j]], arow[j]);
    }
    __syncthreads();
#pragma unroll
    for (int r = 0; r < 16; r++) {
        float* hrow = Hout + ((size_t)b * NPTS + i0 + r) * DIM;
        for (int k = t; k < KC; k += 256) hrow[k] = mishf(acc[r][k]);
    }
}

__global__ void zero_pooled_kernel() {
    g_pooled[blockIdx.x * DIM + threadIdx.x] = 0.f;
}

// ---------------- out = pooled @ Wp + bp ----------------
__global__ void out_kernel(const float* __restrict__ Wp, const float* __restrict__ bp,
                           float* __restrict__ out) {
    int b = blockIdx.x, t = threadIdx.x;  // 32 threads
    if (t < OUTD) {
        const float* p = g_pooled + b * DIM;
        float s = 0.f;
        for (int h = 0; h < DIM; h++) s += p[h] * Wp[h * OUTD + t];
        out[b * OUTD + t] = s + bp[t];
    }
}

// ---------------- host orchestration ----------------
static void run_ctod(const float* X, const float* centers) {
    rowsq_init_kernel<<<dim3(NPTS, BATCH), 128>>>(X);
    for (int it = 0; it < 10; it++) {
        gemm_kernel<0><<<dim3(NPTS / 128, 1, BATCH), 128>>>(
            X, centers, nullptr, nullptr, DIM, KC,
            (size_t)NPTS * DIM, (size_t)KC * DIM, (size_t)0);
        if (it < 9) {
            listbuild_kernel<<<BATCH, 256>>>();
            gather_pass1_kernel<<<dim3(NSLOT, BATCH), 128>>>(X);
            gather_pass2_kernel<<<dim3(KC, BATCH), 128>>>();
        }
    }
}

extern "C" void kernel_launch(void* const* d_in, const int* in_sizes, int n_in,
                              void* d_out, int out_size) {
    const float* x   = (const float*)d_in[0];
    const float* adj = (const float*)d_in[1];
    const float* W   = (const float*)d_in[2];
    const float* bb  = (const float*)d_in[3];
    const float* Wp  = (const float*)d_in[4];
    const float* bp  = (const float*)d_in[5];
    float* out = (float*)d_out;

    float *h0, *h1, *centers;
    cudaGetSymbolAddress((void**)&h0, g_buf0);
    cudaGetSymbolAddress((void**)&h1, g_buf1);
    cudaGetSymbolAddress((void**)&centers, g_centers);

    // Layer 1
    run_ctod(x, centers);
    segsum_mish_kernel<<<dim3(NPTS / 16, BATCH), 256>>>(adj, h0);
    // Layer 2
    run_ctod(h0, centers);
    segsum_mish_kernel<<<dim3(NPTS / 16, BATCH), 256>>>(adj, h1);
    // Layer 3
    run_ctod(h1, centers);
    segsum_mish_kernel<<<dim3(NPTS / 16, BATCH), 256>>>(adj, h0);

    // Final layer: t = h0 @ W, then pooled mish(adj @ t + b)
    gemm_kernel<1><<<dim3(NPTS / 128, 1, BATCH), 128>>>(
        h0, W, h1, nullptr, DIM, DIM,
        (size_t)NPTS * DIM, (size_t)0, (size_t)NPTS * DIM);
    zero_pooled_kernel<<<BATCH, DIM>>>();
    gemm_kernel<2><<<dim3(NPTS / 128, 1, BATCH), 128>>>(
        adj, h1, nullptr, bb, NPTS, DIM,
        (size_t)NPTS * NPTS, (size_t)NPTS * DIM, (size_t)0);
    out_kernel<<<BATCH, 32>>>(Wp, bp, out);
}

// round 11
// speedup vs baseline: 1.2313x; 1.0279x over previous
#include <cuda_runtime.h>
#include <math.h>

#define BATCH 8
#define NPTS  4096
#define DIM   512
#define KC    512
#define OUTD  10
#define NSLOT 768
#define STAGES 4

// ---------------- scratch (static device globals; no allocs) ----------------
__device__ float g_buf0[(size_t)BATCH * NPTS * DIM];   // h row-major
__device__ float g_buf1[(size_t)BATCH * NPTS * DIM];   // h row-major / t
__device__ float g_bufT[(size_t)BATCH * DIM * NPTS];   // current X^T [DIM][NPTS]
__device__ float g_adjT[(size_t)BATCH * NPTS * NPTS];  // adj^T
__device__ float g_centersT[(size_t)BATCH * DIM * KC]; // centers^T [DIM][KC]
__device__ float g_x2[BATCH * NPTS];
__device__ float g_c2[BATCH * KC];
__device__ int g_labels[BATCH * NPTS];
__device__ int g_list[BATCH * NPTS];
__device__ int g_counts[BATCH * KC];
__device__ int g_offs[BATCH * KC];
__device__ int g_choff[BATCH * KC];
__device__ int g_slot_s[BATCH * NSLOT];
__device__ int g_slot_n[BATCH * NSLOT];
__device__ int g_nslots[BATCH];
__device__ float g_partial[(size_t)BATCH * NSLOT * DIM];
__device__ float g_pooled[BATCH * DIM];

__device__ __forceinline__ float mishf(float x) {
    float sp = fmaxf(x, 0.0f) + log1pf(expf(-fabsf(x)));
    return x * tanhf(sp);
}
__device__ __forceinline__ void ffma2(unsigned long long& d, unsigned long long a,
                                      unsigned long long b) {
    asm("fma.rn.f32x2 %0, %1, %2, %0;" : "+l"(d) : "l"(a), "l"(b));
}
__device__ __forceinline__ unsigned long long dup2(unsigned x) {
    unsigned long long r;
    asm("mov.b64 %0, {%1, %1};" : "=l"(r) : "r"(x));
    return r;
}

// ---------------- 32x32 tiled transpose: in [R][C] -> out [C][R] ------------
__global__ void transpose_kernel(const float* __restrict__ in, float* __restrict__ out,
                                 int R, int C) {
    __shared__ float tile[32][33];
    int b = blockIdx.z;
    const float* I = in + (size_t)b * R * C;
    float* O = out + (size_t)b * R * C;
    int r0 = blockIdx.y * 32, c0 = blockIdx.x * 32;
    int tx = threadIdx.x, ty = threadIdx.y;  // 32 x 8
#pragma unroll
    for (int i = 0; i < 32; i += 8)
        tile[ty + i][tx] = I[(size_t)(r0 + ty + i) * C + c0 + tx];
    __syncthreads();
#pragma unroll
    for (int i = 0; i < 32; i += 8)
        O[(size_t)(c0 + ty + i) * R + r0 + tx] = tile[tx][ty + i];
}

// ---------------- row squared norms (row-major X) ----------------
__global__ void rowsq_kernel(const float* __restrict__ X) {
    int b = blockIdx.y, i = blockIdx.x, t = threadIdx.x;  // 128 threads
    const float* row = X + ((size_t)b * NPTS + i) * DIM;
    float s = 0.f;
#pragma unroll
    for (int u = 0; u < 4; u++) { float v = row[t + 128 * u]; s += v * v; }
    for (int o = 16; o > 0; o >>= 1) s += __shfl_down_sync(0xffffffffu, s, o);
    __shared__ float w[4];
    if ((t & 31) == 0) w[t >> 5] = s;
    __syncthreads();
    if (t == 0) g_x2[b * NPTS + i] = w[0] + w[1] + w[2] + w[3];
}

// ---------------- centersT init: copy first KC cols of XT; c2 = x2 ----------
__global__ void initcT_kernel(const float* __restrict__ XT) {
    int b = blockIdx.y, d = blockIdx.x, t = threadIdx.x;  // 128 threads, 4 each
    const float* src = XT + ((size_t)b * DIM + d) * NPTS;
    float* dst = g_centersT + ((size_t)b * DIM + d) * KC;
    *(float4*)(dst + t * 4) = *(const float4*)(src + t * 4);
}
__global__ void c2copy_kernel() {
    int b = blockIdx.x, t = threadIdx.x;  // 512 threads
    g_c2[b * KC + t] = g_x2[b * NPTS + t];
}

// ============================================================================
// f32x2 GEMM core v5: all operands K-major, cp.async 4-stage pipeline,
// 128x128 tile, BK=8, 128 threads, 16x8 microtile, internal N-tile loop.
// AT: [Kd][Ma-lead] (A transposed), B: [Kd][Nn].
// MODE 0: assign (B = centersT) -> argmin labels
// MODE 1: C = A@B plain store
// MODE 2: pooled mish epilogue
// ============================================================================
template <int MODE>
__global__ __launch_bounds__(128, 2) void gemm_kernel(
    const float* __restrict__ AT, const float* __restrict__ B,
    float* __restrict__ C, const float* __restrict__ bias,
    int Kd, int Nn, int Ma, size_t aBatch, size_t bBatch, size_t cBatch) {
    __shared__ __align__(16) float As[STAGES][8][128];
    __shared__ __align__(16) float Bs[STAGES][8][128];
    __shared__ unsigned long long skey[128];
    __shared__ float colsum[128];

    int b = blockIdx.z;
    const float* ATb = AT + (size_t)b * aBatch;
    const float* Bb = B + (size_t)b * bBatch;
    int m0 = blockIdx.x * 128;
    int tid = threadIdx.x;
    int tx = tid & 15, ty = tid >> 4;
    int lkk = tid >> 4, lc = (tid & 15) * 4;  // loader: row kk, float offset

    if (MODE == 0) skey[tid] = 0xFFFFFFFFFFFFFFFFull;

    int nk = Kd >> 3;
    int ntiles = Nn >> 7;
    for (int nt = 0; nt < ntiles; nt++) {
        int n0 = nt << 7;
        unsigned long long acc[8][8];
#pragma unroll
        for (int i = 0; i < 8; i++)
#pragma unroll
            for (int j = 0; j < 8; j++) acc[i][j] = 0ull;

        auto issue = [&](int t) {
            int st = t & (STAGES - 1);
            int krow = (t << 3) + lkk;
            const float* ga = ATb + (size_t)krow * Ma + m0 + lc;
            const float* gb = Bb + (size_t)krow * Nn + n0 + lc;
            unsigned sa = (unsigned)__cvta_generic_to_shared(&As[st][lkk][lc]);
            unsigned sb = (unsigned)__cvta_generic_to_shared(&Bs[st][lkk][lc]);
            asm volatile(
                "cp.async.cg.shared.global [%0], [%1], 16;\n\t"
                "cp.async.cg.shared.global [%2], [%3], 16;\n\t"
                "cp.async.cg.shared.global [%4], [%5], 16;\n\t"
                "cp.async.cg.shared.global [%6], [%7], 16;\n\t"
                "cp.async.commit_group;\n\t" ::
                "r"(sa), "l"(ga), "r"(sa + 256), "l"(ga + 64),
                "r"(sb), "l"(gb), "r"(sb + 256), "l"(gb + 64));
        };

        for (int p = 0; p < STAGES - 1; p++) issue(p);

        for (int t = 0; t < nk; t++) {
            asm volatile("cp.async.wait_group %0;" :: "n"(STAGES - 2));
            __syncthreads();
            if (t + STAGES - 1 < nk) issue(t + STAGES - 1);
            else asm volatile("cp.async.commit_group;");  // keep group count uniform
            int st = t & (STAGES - 1);
#pragma unroll
            for (int kk = 0; kk < 8; kk++) {
                const ulonglong2* apv = (const ulonglong2*)&As[st][kk][ty * 16];
                ulonglong2 A0 = apv[0], A1 = apv[1], A2 = apv[2], A3 = apv[3];
                uint4 b0 = *(const uint4*)&Bs[st][kk][tx * 8];
                uint4 b1 = *(const uint4*)&Bs[st][kk][tx * 8 + 4];
                unsigned long long ap[8] = {A0.x, A0.y, A1.x, A1.y,
                                            A2.x, A2.y, A3.x, A3.y};
                unsigned long long bd[8] = {dup2(b0.x), dup2(b0.y), dup2(b0.z),
                                            dup2(b0.w), dup2(b1.x), dup2(b1.y),
                                            dup2(b1.z), dup2(b1.w)};
#pragma unroll
                for (int i = 0; i < 8; i++)
#pragma unroll
                    for (int j = 0; j < 8; j++) ffma2(acc[i][j], ap[i], bd[j]);
            }
        }
        __syncthreads();  // all warps done with smem buffers before epilogue/next tile

        if (MODE == 0) {
            float c2v[8];
#pragma unroll
            for (int j = 0; j < 8; j++) c2v[j] = g_c2[b * KC + n0 + tx * 8 + j];
            float x2v[16];
#pragma unroll
            for (int i = 0; i < 16; i++)
                x2v[i] = g_x2[b * NPTS + m0 + ty * 16 + i];
#pragma unroll
            for (int mp = 0; mp < 8; mp++) {
#pragma unroll
                for (int h = 0; h < 2; h++) {
                    int rl = ty * 16 + 2 * mp + h;
                    unsigned long long best = 0xFFFFFFFFFFFFFFFFull;
#pragma unroll
                    for (int j = 0; j < 8; j++) {
                        float dot = ((const float*)&acc[mp][j])[h];
                        float d = (x2v[2 * mp + h] + c2v[j]) - 2.0f * dot;
                        unsigned u = __float_as_uint(d);
                        u = (u & 0x80000000u) ? ~u : (u | 0x80000000u);
                        unsigned long long key =
                            ((unsigned long long)u << 32) |
                            (unsigned)(n0 + tx * 8 + j);
                        best = (key < best) ? key : best;
                    }
                    atomicMin(&skey[rl], best);
                }
            }
        } else if (MODE == 1) {
            float* Cb = C + (size_t)b * cBatch;
#pragma unroll
            for (int mp = 0; mp < 8; mp++) {
#pragma unroll
                for (int h = 0; h < 2; h++) {
                    float* p = Cb + (size_t)(m0 + ty * 16 + 2 * mp + h) * Nn +
                               n0 + tx * 8;
                    float4 v0, v1;
#pragma unroll
                    for (int j = 0; j < 4; j++) {
                        (&v0.x)[j] = ((const float*)&acc[mp][j])[h];
                        (&v1.x)[j] = ((const float*)&acc[mp][j + 4])[h];
                    }
                    *(float4*)p = v0;
                    *(float4*)(p + 4) = v1;
                }
            }
        } else {
            colsum[tid] = 0.f;
            float bj[8];
#pragma unroll
            for (int j = 0; j < 8; j++) bj[j] = bias[n0 + tx * 8 + j];
            __syncthreads();
            float part[8] = {0, 0, 0, 0, 0, 0, 0, 0};
#pragma unroll
            for (int mp = 0; mp < 8; mp++)
#pragma unroll
                for (int j = 0; j < 8; j++) {
                    part[j] += mishf(((const float*)&acc[mp][j])[0] + bj[j]);
                    part[j] += mishf(((const float*)&acc[mp][j])[1] + bj[j]);
                }
#pragma unroll
            for (int j = 0; j < 8; j++) atomicAdd(&colsum[tx * 8 + j], part[j]);
            __syncthreads();
            atomicAdd(&g_pooled[b * DIM + n0 + tid], colsum[tid]);
        }
        __syncthreads();
    }

    if (MODE == 0)
        g_labels[b * NPTS + m0 + tid] = (int)(skey[tid] & 0xFFFFFFFFu);
}

// ---------------- parallel stable member-list build + chunk slots -----------
__global__ __launch_bounds__(256) void listbuild_kernel() {
    __shared__ int labs[NPTS];
    __shared__ int cnt[8][KC];
    __shared__ int tot[KC];
    __shared__ int offs[KC];
    __shared__ int schoff[KC];
    int b = blockIdx.x, t = threadIdx.x;
    int w = t >> 5, lane = t & 31;

    for (int idx = t; idx < 8 * KC; idx += 256) ((int*)cnt)[idx] = 0;
    for (int i = t; i < NPTS; i += 256) labs[i] = g_labels[b * NPTS + i];
    __syncthreads();

    for (int r = 0; r < 16; r++) {
        int i = w * 512 + r * 32 + lane;
        atomicAdd(&cnt[w][labs[i]], 1);
    }
    __syncthreads();

    for (int l = t; l < KC; l += 256) {
        int s = 0;
#pragma unroll
        for (int ch = 0; ch < 8; ch++) {
            int c = cnt[ch][l];
            cnt[ch][l] = s;
            s += c;
        }
        tot[l] = s;
    }
    __syncthreads();

    if (t < 32) {
        int carry = 0;
        for (int c = 0; c < KC / 32; c++) {
            int v = tot[c * 32 + t];
            int x = v;
#pragma unroll
            for (int o = 1; o < 32; o <<= 1) {
                int y = __shfl_up_sync(0xffffffffu, x, o);
                if (t >= o) x += y;
            }
            offs[c * 32 + t] = carry + x - v;
            carry += __shfl_sync(0xffffffffu, x, 31);
        }
    } else if (t < 64) {
        int tl = t - 32;
        int carry = 0;
        for (int c = 0; c < KC / 32; c++) {
            int v = (tot[c * 32 + tl] + 15) >> 4;
            int x = v;
#pragma unroll
            for (int o = 1; o < 32; o <<= 1) {
                int y = __shfl_up_sync(0xffffffffu, x, o);
                if (tl >= o) x += y;
            }
            schoff[c * 32 + tl] = carry + x - v;
            carry += __shfl_sync(0xffffffffu, x, 31);
        }
        if (tl == 31) g_nslots[b] = carry;
    }
    __syncthreads();
    for (int l = t; l < KC; l += 256) {
        g_counts[b * KC + l] = tot[l];
        g_offs[b * KC + l] = offs[l];
        g_choff[b * KC + l] = schoff[l];
        int nc = (tot[l] + 15) >> 4;
        int base = schoff[l];
        for (int j = 0; j < nc; j++) {
            g_slot_s[b * NSLOT + base + j] = offs[l] + j * 16;
            g_slot_n[b * NSLOT + base + j] = min(16, tot[l] - j * 16);
        }
    }
    for (int idx = t; idx < 8 * KC; idx += 256) {
        int ch = idx >> 9, l = idx & (KC - 1);
        cnt[ch][l] += offs[l];
    }
    __syncthreads();

    unsigned below = (lane == 0) ? 0u : (0xffffffffu >> (32 - lane));
    for (int r = 0; r < 16; r++) {
        int i = w * 512 + r * 32 + lane;
        int l = labs[i];
        unsigned mask = __match_any_sync(0xffffffffu, l);
        int base = cnt[w][l];
        __syncwarp();
        int rank = __popc(mask & below);
        g_list[b * NPTS + base + rank] = i;
        if (lane == __ffs(mask) - 1) cnt[w][l] = base + __popc(mask);
        __syncwarp();
    }
}

// ---------------- center update pass 1: sum each 16-member chunk ------------
__global__ __launch_bounds__(128) void gather_pass1_kernel(const float* __restrict__ X) {
    int b = blockIdx.y, slot = blockIdx.x, t = threadIdx.x;
    if (slot >= g_nslots[b]) return;
    int s = g_slot_s[b * NSLOT + slot];
    int n = g_slot_n[b * NSLOT + slot];
    const int* lst = g_list + b * NPTS + s;
    const float* Xb = X + (size_t)b * NPTS * DIM;
    float4 a = {0, 0, 0, 0};
    for (int e = 0; e < n; e++) {
        float4 v = *(const float4*)(Xb + (size_t)lst[e] * DIM + t * 4);
        a.x += v.x; a.y += v.y; a.z += v.z; a.w += v.w;
    }
    *(float4*)(g_partial + ((size_t)b * NSLOT + slot) * DIM + t * 4) = a;
}

// ---------------- center update pass 2: combine, divide, write centersT, c2 -
__global__ __launch_bounds__(128) void gather_pass2_kernel() {
    int b = blockIdx.y, k = blockIdx.x, t = threadIdx.x;
    int cnt = g_counts[b * KC + k];
    int c0 = g_choff[b * KC + k];
    int nch = (cnt + 15) >> 4;
    float* cT = g_centersT + (size_t)b * DIM * KC;
    float4 v;
    if (cnt > 0) {
        float4 a = {0, 0, 0, 0};
        for (int c = 0; c < nch; c++) {
            float4 p = *(const float4*)(g_partial + ((size_t)b * NSLOT + c0 + c) * DIM + t * 4);
            a.x += p.x; a.y += p.y; a.z += p.z; a.w += p.w;
        }
        float cf = (float)cnt;
        v = make_float4(a.x / cf, a.y / cf, a.z / cf, a.w / cf);
        cT[(size_t)(t * 4 + 0) * KC + k] = v.x;
        cT[(size_t)(t * 4 + 1) * KC + k] = v.y;
        cT[(size_t)(t * 4 + 2) * KC + k] = v.z;
        cT[(size_t)(t * 4 + 3) * KC + k] = v.w;
    } else {
        v.x = cT[(size_t)(t * 4 + 0) * KC + k];
        v.y = cT[(size_t)(t * 4 + 1) * KC + k];
        v.z = cT[(size_t)(t * 4 + 2) * KC + k];
        v.w = cT[(size_t)(t * 4 + 3) * KC + k];
    }
    float sq = v.x * v.x + v.y * v.y + v.z * v.z + v.w * v.w;
    for (int o = 16; o > 0; o >>= 1) sq += __shfl_down_sync(0xffffffffu, sq, o);
    __shared__ float w[4];
    if ((t & 31) == 0) w[t >> 5] = sq;
    __syncthreads();
    if (t == 0) g_c2[b * KC + k] = w[0] + w[1] + w[2] + w[3];
}

// ------- h_next = mish(adj @ one_hot(labels)), 16 rows/block; writes h & hT -
__global__ __launch_bounds__(256) void segsum_mish_kernel(const float* __restrict__ adj,
                                                          float* __restrict__ Hout,
                                                          float* __restrict__ HoutT) {
    int b = blockIdx.y, i0 = blockIdx.x * 16, t = threadIdx.x;  // 256 threads
    __shared__ float acc[16][KC];            // 32KB
    __shared__ unsigned short labs[NPTS];    // 8KB
    const int* lb = g_labels + b * NPTS;
    for (int j = t; j < NPTS; j += 256) labs[j] = (unsigned short)lb[j];
#pragma unroll
    for (int r = 0; r < 16; r++)
        for (int k = t; k < KC; k += 256) acc[r][k] = 0.f;
    __syncthreads();
#pragma unroll
    for (int r = 0; r < 16; r++) {
        const float* arow = adj + ((size_t)b * NPTS + i0 + r) * NPTS;
        for (int j = t; j < NPTS; j += 256) atomicAdd(&acc[r][labs[j]], arow[j]);
    }
    __syncthreads();
    for (int k = t; k < KC; k += 256) {
        float tmp[16];
#pragma unroll
        for (int r = 0; r < 16; r++) tmp[r] = mishf(acc[r][k]);
#pragma unroll
        for (int r = 0; r < 16; r++)
            Hout[((size_t)b * NPTS + i0 + r) * DIM + k] = tmp[r];
        float4* dstT = (float4*)(HoutT + ((size_t)b * DIM + k) * NPTS + i0);
#pragma unroll
        for (int q = 0; q < 4; q++)
            dstT[q] = make_float4(tmp[q * 4], tmp[q * 4 + 1], tmp[q * 4 + 2], tmp[q * 4 + 3]);
    }
}

__global__ void zero_pooled_kernel() {
    g_pooled[blockIdx.x * DIM + threadIdx.x] = 0.f;
}

// ---------------- out = pooled @ Wp + bp ----------------
__global__ void out_kernel(const float* __restrict__ Wp, const float* __restrict__ bp,
                           float* __restrict__ out) {
    int b = blockIdx.x, t = threadIdx.x;  // 32 threads
    if (t < OUTD) {
        const float* p = g_pooled + b * DIM;
        float s = 0.f;
        for (int h = 0; h < DIM; h++) s += p[h] * Wp[h * OUTD + t];
        out[b * OUTD + t] = s + bp[t];
    }
}

// ---------------- host orchestration ----------------
static void run_ctod(const float* X, const float* XT, const float* centersT) {
    rowsq_kernel<<<dim3(NPTS, BATCH), 128>>>(X);
    initcT_kernel<<<dim3(DIM, BATCH), 128>>>(XT);
    c2copy_kernel<<<BATCH, KC>>>();
    for (int it = 0; it < 10; it++) {
        gemm_kernel<0><<<dim3(NPTS / 128, 1, BATCH), 128>>>(
            XT, centersT, nullptr, nullptr, DIM, KC, NPTS,
            (size_t)DIM * NPTS, (size_t)DIM * KC, (size_t)0);
        if (it < 9) {
            listbuild_kernel<<<BATCH, 256>>>();
            gather_pass1_kernel<<<dim3(NSLOT, BATCH), 128>>>(X);
            gather_pass2_kernel<<<dim3(KC, BATCH), 128>>>();
        }
    }
}

extern "C" void kernel_launch(void* const* d_in, const int* in_sizes, int n_in,
                              void* d_out, int out_size) {
    const float* x   = (const float*)d_in[0];
    const float* adj = (const float*)d_in[1];
    const float* W   = (const float*)d_in[2];
    const float* bb  = (const float*)d_in[3];
    const float* Wp  = (const float*)d_in[4];
    const float* bp  = (const float*)d_in[5];
    float* out = (float*)d_out;

    float *h0, *h1, *hT, *adjT, *centersT;
    cudaGetSymbolAddress((void**)&h0, g_buf0);
    cudaGetSymbolAddress((void**)&h1, g_buf1);
    cudaGetSymbolAddress((void**)&hT, g_bufT);
    cudaGetSymbolAddress((void**)&adjT, g_adjT);
    cudaGetSymbolAddress((void**)&centersT, g_centersT);

    // one-time transposes
    transpose_kernel<<<dim3(DIM / 32, NPTS / 32, BATCH), dim3(32, 8)>>>(x, hT, NPTS, DIM);
    transpose_kernel<<<dim3(NPTS / 32, NPTS / 32, BATCH), dim3(32, 8)>>>(adj, adjT, NPTS, NPTS);

    // Layer 1: ctod(x) -> segsum -> h0 (+ h0T in hT)
    run_ctod(x, hT, centersT);
    segsum_mish_kernel<<<dim3(NPTS / 16, BATCH), 256>>>(adj, h0, hT);
    // Layer 2
    run_ctod(h0, hT, centersT);
    segsum_mish_kernel<<<dim3(NPTS / 16, BATCH), 256>>>(adj, h1, hT);
    // Layer 3
    run_ctod(h1, hT, centersT);
    segsum_mish_kernel<<<dim3(NPTS / 16, BATCH), 256>>>(adj, h0, hT);

    // Final layer: t = h0 @ W (A = h0T in hT), then pooled mish(adj @ t + b)
    gemm_kernel<1><<<dim3(NPTS / 128, 1, BATCH), 128>>>(
        hT, W, h1, nullptr, DIM, DIM, NPTS,
        (size_t)DIM * NPTS, (size_t)0, (size_t)NPTS * DIM);
    zero_pooled_kernel<<<BATCH, DIM>>>();
    gemm_kernel<2><<<dim3(NPTS / 128, 1, BATCH), 128>>>(
        adjT, h1, nullptr, bb, NPTS, DIM, NPTS,
        (size_t)NPTS * NPTS, (size_t)NPTS * DIM, (size_t)0);
    out_kernel<<<BATCH, 32>>>(Wp, bp, out);
}

// round 15
// speedup vs baseline: 1.2507x; 1.0158x over previous
#include <cuda_runtime.h>
#include <math.h>

#define BATCH 8
#define NPTS  4096
#define DIM   512
#define KC    512
#define OUTD  10
#define NSLOT 768
#define STAGES 4

// ---------------- scratch (static device globals; no allocs) ----------------
__device__ float g_buf0[(size_t)BATCH * NPTS * DIM];
__device__ float g_buf1[(size_t)BATCH * NPTS * DIM];
__device__ float g_bufT[(size_t)BATCH * DIM * NPTS];   // current X^T [DIM][NPTS]
__device__ float g_adjT[(size_t)BATCH * NPTS * NPTS];  // adj^T
__device__ float g_centersT[(size_t)BATCH * DIM * KC]; // centers^T [DIM][KC]
__device__ float g_x2[BATCH * NPTS];
__device__ float g_c2[BATCH * KC];
__device__ int g_labels[BATCH * NPTS];
__device__ int g_list[BATCH * NPTS];
__device__ int g_counts[BATCH * KC];
__device__ int g_offs[BATCH * KC];
__device__ int g_choff[BATCH * KC];
__device__ int g_slot_s[BATCH * NSLOT];
__device__ int g_slot_n[BATCH * NSLOT];
__device__ int g_nslots[BATCH];
__device__ float g_partial[(size_t)BATCH * NSLOT * DIM];
__device__ float g_pooled[BATCH * DIM];

__device__ __forceinline__ float mishf(float x) {
    float sp = fmaxf(x, 0.0f) + log1pf(expf(-fabsf(x)));
    return x * tanhf(sp);
}
__device__ __forceinline__ void ffma2(unsigned long long& d, unsigned long long a,
                                      unsigned long long b) {
    asm("fma.rn.f32x2 %0, %1, %2, %0;" : "+l"(d) : "l"(a), "l"(b));
}
__device__ __forceinline__ unsigned long long dup2(unsigned x) {
    unsigned long long r;
    asm("mov.b64 %0, {%1, %1};" : "=l"(r) : "r"(x));
    return r;
}

// ---------------- 32x32 tiled transpose: in [R][C] -> out [C][R] ------------
__global__ void transpose_kernel(const float* __restrict__ in, float* __restrict__ out,
                                 int R, int C) {
    __shared__ float tile[32][33];
    int b = blockIdx.z;
    const float* I = in + (size_t)b * R * C;
    float* O = out + (size_t)b * R * C;
    int r0 = blockIdx.y * 32, c0 = blockIdx.x * 32;
    int tx = threadIdx.x, ty = threadIdx.y;  // 32 x 8
#pragma unroll
    for (int i = 0; i < 32; i += 8)
        tile[ty + i][tx] = I[(size_t)(r0 + ty + i) * C + c0 + tx];
    __syncthreads();
#pragma unroll
    for (int i = 0; i < 32; i += 8)
        O[(size_t)(c0 + ty + i) * R + r0 + tx] = tile[tx][ty + i];
}

// ---------------- row squared norms; c2 for initial centers (rows < KC) -----
__global__ void rowsq_kernel(const float* __restrict__ X) {
    int b = blockIdx.y, i = blockIdx.x, t = threadIdx.x;  // 128 threads
    const float* row = X + ((size_t)b * NPTS + i) * DIM;
    float s = 0.f;
#pragma unroll
    for (int u = 0; u < 4; u++) { float v = row[t + 128 * u]; s += v * v; }
    for (int o = 16; o > 0; o >>= 1) s += __shfl_down_sync(0xffffffffu, s, o);
    __shared__ float w[4];
    if ((t & 31) == 0) w[t >> 5] = s;
    __syncthreads();
    if (t == 0) {
        float tot = w[0] + w[1] + w[2] + w[3];
        g_x2[b * NPTS + i] = tot;
        if (i < KC) g_c2[b * KC + i] = tot;  // centers0 = X[:KC]
    }
}

// ---------------- centersT init: copy first KC cols of XT ----------
__global__ void initcT_kernel(const float* __restrict__ XT) {
    int b = blockIdx.y, d = blockIdx.x, t = threadIdx.x;  // 128 threads, 4 each
    const float* src = XT + ((size_t)b * DIM + d) * NPTS;
    float* dst = g_centersT + ((size_t)b * DIM + d) * KC;
    *(float4*)(dst + t * 4) = *(const float4*)(src + t * 4);
}

// ============================================================================
// f32x2 GEMM core: all operands K-major, cp.async 4-stage pipeline,
// 128x128 tile, BK=8, 128 threads, 16x8 microtile, internal N-tile loop.
// AT: [Kd][Ma-lead] (A transposed), B: [Kd][Nn].
// MODE 0: assign (B = centersT) -> argmin labels
// MODE 1: C = A@B plain store
// MODE 2: pooled mish epilogue
// ============================================================================
template <int MODE>
__global__ __launch_bounds__(128, 2) void gemm_kernel(
    const float* __restrict__ AT, const float* __restrict__ B,
    float* __restrict__ C, const float* __restrict__ bias,
    int Kd, int Nn, int Ma, size_t aBatch, size_t bBatch, size_t cBatch) {
    __shared__ __align__(16) float As[STAGES][8][128];
    __shared__ __align__(16) float Bs[STAGES][8][128];
    __shared__ unsigned long long skey[128];
    __shared__ float colsum[128];

    int b = blockIdx.z;
    const float* ATb = AT + (size_t)b * aBatch;
    const float* Bb = B + (size_t)b * bBatch;
    int m0 = blockIdx.x * 128;
    int tid = threadIdx.x;
    int tx = tid & 15, ty = tid >> 4;
    int lkk = tid >> 4, lc = (tid & 15) * 4;  // loader: row kk, float offset

    if (MODE == 0) skey[tid] = 0xFFFFFFFFFFFFFFFFull;

    int nk = Kd >> 3;
    int ntiles = Nn >> 7;
    for (int nt = 0; nt < ntiles; nt++) {
        int n0 = nt << 7;
        unsigned long long acc[8][8];
#pragma unroll
        for (int i = 0; i < 8; i++)
#pragma unroll
            for (int j = 0; j < 8; j++) acc[i][j] = 0ull;

        auto issue = [&](int t) {
            int st = t & (STAGES - 1);
            int krow = (t << 3) + lkk;
            const float* ga = ATb + (size_t)krow * Ma + m0 + lc;
            const float* gb = Bb + (size_t)krow * Nn + n0 + lc;
            unsigned sa = (unsigned)__cvta_generic_to_shared(&As[st][lkk][lc]);
            unsigned sb = (unsigned)__cvta_generic_to_shared(&Bs[st][lkk][lc]);
            asm volatile(
                "cp.async.cg.shared.global [%0], [%1], 16;\n\t"
                "cp.async.cg.shared.global [%2], [%3], 16;\n\t"
                "cp.async.cg.shared.global [%4], [%5], 16;\n\t"
                "cp.async.cg.shared.global [%6], [%7], 16;\n\t"
                "cp.async.commit_group;\n\t" ::
                "r"(sa), "l"(ga), "r"(sa + 256), "l"(ga + 64),
                "r"(sb), "l"(gb), "r"(sb + 256), "l"(gb + 64));
        };

        for (int p = 0; p < STAGES - 1; p++) issue(p);

        for (int t = 0; t < nk; t++) {
            asm volatile("cp.async.wait_group %0;" :: "n"(STAGES - 2));
            __syncthreads();
            if (t + STAGES - 1 < nk) issue(t + STAGES - 1);
            else asm volatile("cp.async.commit_group;");  // keep group count uniform
            int st = t & (STAGES - 1);
#pragma unroll
            for (int kk = 0; kk < 8; kk++) {
                const ulonglong2* apv = (const ulonglong2*)&As[st][kk][ty * 16];
                ulonglong2 A0 = apv[0], A1 = apv[1], A2 = apv[2], A3 = apv[3];
                uint4 b0 = *(const uint4*)&Bs[st][kk][tx * 8];
                uint4 b1 = *(const uint4*)&Bs[st][kk][tx * 8 + 4];
                unsigned long long ap[8] = {A0.x, A0.y, A1.x, A1.y,
                                            A2.x, A2.y, A3.x, A3.y};
                unsigned long long bd[8] = {dup2(b0.x), dup2(b0.y), dup2(b0.z),
                                            dup2(b0.w), dup2(b1.x), dup2(b1.y),
                                            dup2(b1.z), dup2(b1.w)};
#pragma unroll
                for (int i = 0; i < 8; i++)
#pragma unroll
                    for (int j = 0; j < 8; j++) ffma2(acc[i][j], ap[i], bd[j]);
            }
        }
        __syncthreads();  // all warps done with smem buffers before epilogue/next tile

        if (MODE == 0) {
            float c2v[8];
#pragma unroll
            for (int j = 0; j < 8; j++) c2v[j] = g_c2[b * KC + n0 + tx * 8 + j];
            float x2v[16];
#pragma unroll
            for (int i = 0; i < 16; i++)
                x2v[i] = g_x2[b * NPTS + m0 + ty * 16 + i];
#pragma unroll
            for (int mp = 0; mp < 8; mp++) {
#pragma unroll
                for (int h = 0; h < 2; h++) {
                    int rl = ty * 16 + 2 * mp + h;
                    unsigned long long best = 0xFFFFFFFFFFFFFFFFull;
#pragma unroll
                    for (int j = 0; j < 8; j++) {
                        float dot = ((const float*)&acc[mp][j])[h];
                        float d = (x2v[2 * mp + h] + c2v[j]) - 2.0f * dot;
                        unsigned u = __float_as_uint(d);
                        u = (u & 0x80000000u) ? ~u : (u | 0x80000000u);
                        unsigned long long key =
                            ((unsigned long long)u << 32) |
                            (unsigned)(n0 + tx * 8 + j);
                        best = (key < best) ? key : best;
                    }
                    atomicMin(&skey[rl], best);
                }
            }
        } else if (MODE == 1) {
            float* Cb = C + (size_t)b * cBatch;
#pragma unroll
            for (int mp = 0; mp < 8; mp++) {
#pragma unroll
                for (int h = 0; h < 2; h++) {
                    float* p = Cb + (size_t)(m0 + ty * 16 + 2 * mp + h) * Nn +
                               n0 + tx * 8;
                    float4 v0, v1;
#pragma unroll
                    for (int j = 0; j < 4; j++) {
                        (&v0.x)[j] = ((const float*)&acc[mp][j])[h];
                        (&v1.x)[j] = ((const float*)&acc[mp][j + 4])[h];
                    }
                    *(float4*)p = v0;
                    *(float4*)(p + 4) = v1;
                }
            }
        } else {
            colsum[tid] = 0.f;
            float bj[8];
#pragma unroll
            for (int j = 0; j < 8; j++) bj[j] = bias[n0 + tx * 8 + j];
            __syncthreads();
            float part[8] = {0, 0, 0, 0, 0, 0, 0, 0};
#pragma unroll
            for (int mp = 0; mp < 8; mp++)
#pragma unroll
                for (int j = 0; j < 8; j++) {
                    part[j] += mishf(((const float*)&acc[mp][j])[0] + bj[j]);
                    part[j] += mishf(((const float*)&acc[mp][j])[1] + bj[j]);
                }
#pragma unroll
            for (int j = 0; j < 8; j++) atomicAdd(&colsum[tx * 8 + j], part[j]);
            __syncthreads();
            atomicAdd(&g_pooled[b * DIM + n0 + tid], colsum[tid]);
        }
        __syncthreads();
    }

    if (MODE == 0)
        g_labels[b * NPTS + m0 + tid] = (int)(skey[tid] & 0xFFFFFFFFu);
}

// ---------------- parallel stable member-list build + chunk slots -----------
__global__ __launch_bounds__(256) void listbuild_kernel() {
    __shared__ int labs[NPTS];
    __shared__ int cnt[8][KC];
    __shared__ int tot[KC];
    __shared__ int offs[KC];
    __shared__ int schoff[KC];
    int b = blockIdx.x, t = threadIdx.x;
    int w = t >> 5, lane = t & 31;

    for (int idx = t; idx < 8 * KC; idx += 256) ((int*)cnt)[idx] = 0;
    for (int i = t; i < NPTS; i += 256) labs[i] = g_labels[b * NPTS + i];
    __syncthreads();

    for (int r = 0; r < 16; r++) {
        int i = w * 512 + r * 32 + lane;
        atomicAdd(&cnt[w][labs[i]], 1);
    }
    __syncthreads();

    for (int l = t; l < KC; l += 256) {
        int s = 0;
#pragma unroll
        for (int ch = 0; ch < 8; ch++) {
            int c = cnt[ch][l];
            cnt[ch][l] = s;
            s += c;
        }
        tot[l] = s;
    }
    __syncthreads();

    if (t < 32) {
        int carry = 0;
        for (int c = 0; c < KC / 32; c++) {
            int v = tot[c * 32 + t];
            int x = v;
#pragma unroll
            for (int o = 1; o < 32; o <<= 1) {
                int y = __shfl_up_sync(0xffffffffu, x, o);
                if (t >= o) x += y;
            }
            offs[c * 32 + t] = carry + x - v;
            carry += __shfl_sync(0xffffffffu, x, 31);
        }
    } else if (t < 64) {
        int tl = t - 32;
        int carry = 0;
        for (int c = 0; c < KC / 32; c++) {
            int v = (tot[c * 32 + tl] + 15) >> 4;
            int x = v;
#pragma unroll
            for (int o = 1; o < 32; o <<= 1) {
                int y = __shfl_up_sync(0xffffffffu, x, o);
                if (tl >= o) x += y;
            }
            schoff[c * 32 + tl] = carry + x - v;
            carry += __shfl_sync(0xffffffffu, x, 31);
        }
        if (tl == 31) g_nslots[b] = carry;
    }
    __syncthreads();
    for (int l = t; l < KC; l += 256) {
        g_counts[b * KC + l] = tot[l];
        g_offs[b * KC + l] = offs[l];
        g_choff[b * KC + l] = schoff[l];
        int nc = (tot[l] + 15) >> 4;
        int base = schoff[l];
        for (int j = 0; j < nc; j++) {
            g_slot_s[b * NSLOT + base + j] = offs[l] + j * 16;
            g_slot_n[b * NSLOT + base + j] = min(16, tot[l] - j * 16);
        }
    }
    for (int idx = t; idx < 8 * KC; idx += 256) {
        int ch = idx >> 9, l = idx & (KC - 1);
        cnt[ch][l] += offs[l];
    }
    __syncthreads();

    unsigned below = (lane == 0) ? 0u : (0xffffffffu >> (32 - lane));
    for (int r = 0; r < 16; r++) {
        int i = w * 512 + r * 32 + lane;
        int l = labs[i];
        unsigned mask = __match_any_sync(0xffffffffu, l);
        int base = cnt[w][l];
        __syncwarp();
        int rank = __popc(mask & below);
        g_list[b * NPTS + base + rank] = i;
        if (lane == __ffs(mask) - 1) cnt[w][l] = base + __popc(mask);
        __syncwarp();
    }
}

// ---------------- center update pass 1: sum each 16-member chunk ------------
__global__ __launch_bounds__(128) void gather_pass1_kernel(const float* __restrict__ X) {
    int b = blockIdx.y, slot = blockIdx.x, t = threadIdx.x;
    if (slot >= g_nslots[b]) return;
    int s = g_slot_s[b * NSLOT + slot];
    int n = g_slot_n[b * NSLOT + slot];
    const int* lst = g_list + b * NPTS + s;
    const float* Xb = X + (size_t)b * NPTS * DIM;
    float4 a = {0, 0, 0, 0};
    for (int e = 0; e < n; e++) {
        float4 v = *(const float4*)(Xb + (size_t)lst[e] * DIM + t * 4);
        a.x += v.x; a.y += v.y; a.z += v.z; a.w += v.w;
    }
    *(float4*)(g_partial + ((size_t)b * NSLOT + slot) * DIM + t * 4) = a;
}

// ---------------- center update pass 2: combine chunks, write centersT, c2 --
__global__ __launch_bounds__(128) void gather_pass2_kernel() {
    int b = blockIdx.y, k = blockIdx.x, t = threadIdx.x;
    int cnt = g_counts[b * KC + k];
    int c0 = g_choff[b * KC + k];
    int nch = (cnt + 15) >> 4;
    float* cT = g_centersT + (size_t)b * DIM * KC;
    float4 v;
    if (cnt > 0) {
        float4 a = {0, 0, 0, 0};
        for (int c = 0; c < nch; c++) {
            float4 p = *(const float4*)(g_partial + ((size_t)b * NSLOT + c0 + c) * DIM + t * 4);
            a.x += p.x; a.y += p.y; a.z += p.z; a.w += p.w;
        }
        float cf = (float)cnt;
        v = make_float4(a.x / cf, a.y / cf, a.z / cf, a.w / cf);
        cT[(size_t)(t * 4 + 0) * KC + k] = v.x;
        cT[(size_t)(t * 4 + 1) * KC + k] = v.y;
        cT[(size_t)(t * 4 + 2) * KC + k] = v.z;
        cT[(size_t)(t * 4 + 3) * KC + k] = v.w;
    } else {
        v.x = cT[(size_t)(t * 4 + 0) * KC + k];
        v.y = cT[(size_t)(t * 4 + 1) * KC + k];
        v.z = cT[(size_t)(t * 4 + 2) * KC + k];
        v.w = cT[(size_t)(t * 4 + 3) * KC + k];
    }
    float sq = v.x * v.x + v.y * v.y + v.z * v.z + v.w * v.w;
    for (int o = 16; o > 0; o >>= 1) sq += __shfl_down_sync(0xffffffffu, sq, o);
    __shared__ float w[4];
    if ((t & 31) == 0) w[t >> 5] = sq;
    __syncthreads();
    if (t == 0) g_c2[b * KC + k] = w[0] + w[1] + w[2] + w[3];
}

// ------- h_next = mish(adj @ one_hot(labels)), 16 rows/block; writes h & hT -
// Atomic phase: each warp owns 2 rows -> contention pool 256 -> 32 threads.
__global__ __launch_bounds__(256) void segsum_mish_kernel(const float* __restrict__ adj,
                                                          float* __restrict__ Hout,
                                                          float* __restrict__ HoutT) {
    int b = blockIdx.y, i0 = blockIdx.x * 16, t = threadIdx.x;  // 256 threads
    int w = t >> 5, lane = t & 31;
    __shared__ float acc[16][KC];            // 32KB
    __shared__ unsigned short labs[NPTS];    // 8KB
    const int* lb = g_labels + b * NPTS;
    for (int j = t; j < NPTS; j += 256) labs[j] = (unsigned short)lb[j];
#pragma unroll
    for (int r = 0; r < 16; r++)
        for (int k = t; k < KC; k += 256) acc[r][k] = 0.f;
    __syncthreads();
#pragma unroll
    for (int rr = 0; rr < 2; rr++) {
        int r = w * 2 + rr;
        const float* arow = adj + ((size_t)b * NPTS + i0 + r) * NPTS;
        for (int j = lane; j < NPTS; j += 32) atomicAdd(&acc[r][labs[j]], arow[j]);
    }
    __syncthreads();
    for (int k = t; k < KC; k += 256) {
        float tmp[16];
#pragma unroll
        for (int r = 0; r < 16; r++) tmp[r] = mishf(acc[r][k]);
#pragma unroll
        for (int r = 0; r < 16; r++)
            Hout[((size_t)b * NPTS + i0 + r) * DIM + k] = tmp[r];
        float4* dstT = (float4*)(HoutT + ((size_t)b * DIM + k) * NPTS + i0);
#pragma unroll
        for (int q = 0; q < 4; q++)
            dstT[q] = make_float4(tmp[q * 4], tmp[q * 4 + 1], tmp[q * 4 + 2], tmp[q * 4 + 3]);
    }
}

__global__ void zero_pooled_kernel() {
    g_pooled[blockIdx.x * DIM + threadIdx.x] = 0.f;
}

// ---------------- out = pooled @ Wp + bp ----------------
__global__ void out_kernel(const float* __restrict__ Wp, const float* __restrict__ bp,
                           float* __restrict__ out) {
    int b = blockIdx.x, t = threadIdx.x;  // 32 threads
    if (t < OUTD) {
        const float* p = g_pooled + b * DIM;
        float s = 0.f;
        for (int h = 0; h < DIM; h++) s += p[h] * Wp[h * OUTD + t];
        out[b * OUTD + t] = s + bp[t];
    }
}

// ---------------- host orchestration ----------------
static void run_ctod(const float* X, const float* XT, const float* centersT) {
    rowsq_kernel<<<dim3(NPTS, BATCH), 128>>>(X);   // also seeds g_c2 (rows < KC)
    initcT_kernel<<<dim3(DIM, BATCH), 128>>>(XT);
    for (int it = 0; it < 10; it++) {
        gemm_kernel<0><<<dim3(NPTS / 128, 1, BATCH), 128>>>(
            XT, centersT, nullptr, nullptr, DIM, KC, NPTS,
            (size_t)DIM * NPTS, (size_t)DIM * KC, (size_t)0);
        if (it < 9) {
            listbuild_kernel<<<BATCH, 256>>>();
            gather_pass1_kernel<<<dim3(NSLOT, BATCH), 128>>>(X);
            gather_pass2_kernel<<<dim3(KC, BATCH), 128>>>();
        }
    }
}

extern "C" void kernel_launch(void* const* d_in, const int* in_sizes, int n_in,
                              void* d_out, int out_size) {
    const float* x   = (const float*)d_in[0];
    const float* adj = (const float*)d_in[1];
    const float* W   = (const float*)d_in[2];
    const float* bb  = (const float*)d_in[3];
    const float* Wp  = (const float*)d_in[4];
    const float* bp  = (const float*)d_in[5];
    float* out = (float*)d_out;

    float *h0, *h1, *hT, *adjT, *centersT;
    cudaGetSymbolAddress((void**)&h0, g_buf0);
    cudaGetSymbolAddress((void**)&h1, g_buf1);
    cudaGetSymbolAddress((void**)&hT, g_bufT);
    cudaGetSymbolAddress((void**)&adjT, g_adjT);
    cudaGetSymbolAddress((void**)&centersT, g_centersT);

    // one-time transposes
    transpose_kernel<<<dim3(DIM / 32, NPTS / 32, BATCH), dim3(32, 8)>>>(x, hT, NPTS, DIM);
    transpose_kernel<<<dim3(NPTS / 32, NPTS / 32, BATCH), dim3(32, 8)>>>(adj, adjT, NPTS, NPTS);

    // Layer 1: ctod(x) -> segsum -> h0 (+ h0T in hT)
    run_ctod(x, hT, centersT);
    segsum_mish_kernel<<<dim3(NPTS / 16, BATCH), 256>>>(adj, h0, hT);
    // Layer 2
    run_ctod(h0, hT, centersT);
    segsum_mish_kernel<<<dim3(NPTS / 16, BATCH), 256>>>(adj, h1, hT);
    // Layer 3
    run_ctod(h1, hT, centersT);
    segsum_mish_kernel<<<dim3(NPTS / 16, BATCH), 256>>>(adj, h0, hT);

    // Final layer: t = h0 @ W (A = h0T in hT), then pooled mish(adj @ t + b)
    gemm_kernel<1><<<dim3(NPTS / 128, 1, BATCH), 128>>>(
        hT, W, h1, nullptr, DIM, DIM, NPTS,
        (size_t)DIM * NPTS, (size_t)0, (size_t)NPTS * DIM);
    zero_pooled_kernel<<<BATCH, DIM>>>();
    gemm_kernel<2><<<dim3(NPTS / 128, 1, BATCH), 128>>>(
        adjT, h1, nullptr, bb, NPTS, DIM, NPTS,
        (size_t)NPTS * NPTS, (size_t)NPTS * DIM, (size_t)0);
    out_kernel<<<BATCH, 32>>>(Wp, bp, out);
}

// round 17
// speedup vs baseline: 1.2557x; 1.0040x over previous
#include <cuda_runtime.h>
#include <math.h>

#define BATCH 8
#define NPTS  4096
#define DIM   512
#define KC    512
#define OUTD  10
#define NSLOT 768
#define STAGES 8
// dynamic smem for gemm: As[8][8][128] + Bs[8][8][128] + skey + colsum
#define GEMM_SMEM (2 * STAGES * 4096 + 1024 + 512)

// ---------------- scratch (static device globals; no allocs) ----------------
__device__ float g_buf0[(size_t)BATCH * NPTS * DIM];
__device__ float g_buf1[(size_t)BATCH * NPTS * DIM];
__device__ float g_bufT[(size_t)BATCH * DIM * NPTS];   // current X^T [DIM][NPTS]
__device__ float g_adjT[(size_t)BATCH * NPTS * NPTS];  // adj^T
__device__ float g_centersT[(size_t)BATCH * DIM * KC]; // centers^T [DIM][KC]
__device__ float g_x2[BATCH * NPTS];
__device__ float g_c2[BATCH * KC];
__device__ int g_labels[BATCH * NPTS];
__device__ int g_list[BATCH * NPTS];
__device__ int g_counts[BATCH * KC];
__device__ int g_offs[BATCH * KC];
__device__ int g_choff[BATCH * KC];
__device__ int g_slot_s[BATCH * NSLOT];
__device__ int g_slot_n[BATCH * NSLOT];
__device__ int g_nslots[BATCH];
__device__ float g_partial[(size_t)BATCH * NSLOT * DIM];
__device__ float g_pooled[BATCH * DIM];

__device__ __forceinline__ float mishf(float x) {
    float sp = fmaxf(x, 0.0f) + log1pf(expf(-fabsf(x)));
    return x * tanhf(sp);
}
__device__ __forceinline__ void ffma2(unsigned long long& d, unsigned long long a,
                                      unsigned long long b) {
    asm("fma.rn.f32x2 %0, %1, %2, %0;" : "+l"(d) : "l"(a), "l"(b));
}
__device__ __forceinline__ unsigned long long dup2(unsigned x) {
    unsigned long long r;
    asm("mov.b64 %0, {%1, %1};" : "=l"(r) : "r"(x));
    return r;
}

// ---------------- 32x32 tiled transpose: in [R][C] -> out [C][R] ------------
__global__ void transpose_kernel(const float* __restrict__ in, float* __restrict__ out,
                                 int R, int C) {
    __shared__ float tile[32][33];
    int b = blockIdx.z;
    const float* I = in + (size_t)b * R * C;
    float* O = out + (size_t)b * R * C;
    int r0 = blockIdx.y * 32, c0 = blockIdx.x * 32;
    int tx = threadIdx.x, ty = threadIdx.y;  // 32 x 8
#pragma unroll
    for (int i = 0; i < 32; i += 8)
        tile[ty + i][tx] = I[(size_t)(r0 + ty + i) * C + c0 + tx];
    __syncthreads();
#pragma unroll
    for (int i = 0; i < 32; i += 8)
        O[(size_t)(c0 + ty + i) * R + r0 + tx] = tile[tx][ty + i];
}

// ---------------- row squared norms; c2 for initial centers (rows < KC) -----
__global__ void rowsq_kernel(const float* __restrict__ X) {
    int b = blockIdx.y, i = blockIdx.x, t = threadIdx.x;  // 128 threads
    const float* row = X + ((size_t)b * NPTS + i) * DIM;
    float s = 0.f;
#pragma unroll
    for (int u = 0; u < 4; u++) { float v = row[t + 128 * u]; s += v * v; }
    for (int o = 16; o > 0; o >>= 1) s += __shfl_down_sync(0xffffffffu, s, o);
    __shared__ float w[4];
    if ((t & 31) == 0) w[t >> 5] = s;
    __syncthreads();
    if (t == 0) {
        float tot = w[0] + w[1] + w[2] + w[3];
        g_x2[b * NPTS + i] = tot;
        if (i < KC) g_c2[b * KC + i] = tot;  // centers0 = X[:KC]
    }
}

// ---------------- centersT init: copy first KC cols of XT ----------
__global__ void initcT_kernel(const float* __restrict__ XT) {
    int b = blockIdx.y, d = blockIdx.x, t = threadIdx.x;  // 128 threads, 4 each
    const float* src = XT + ((size_t)b * DIM + d) * NPTS;
    float* dst = g_centersT + ((size_t)b * DIM + d) * KC;
    *(float4*)(dst + t * 4) = *(const float4*)(src + t * 4);
}

// ============================================================================
// f32x2 GEMM core: all operands K-major, cp.async 8-stage pipeline (dyn smem),
// 128x128 tile, BK=8, 128 threads, 16x8 microtile, internal N-tile loop.
// AT: [Kd][Ma-lead] (A transposed), B: [Kd][Nn].
// MODE 0: assign (B = centersT) -> argmin labels
// MODE 1: C = A@B plain store
// MODE 2: pooled mish epilogue
// ============================================================================
template <int MODE>
__global__ __launch_bounds__(128, 2) void gemm_kernel(
    const float* __restrict__ AT, const float* __restrict__ B,
    float* __restrict__ C, const float* __restrict__ bias,
    int Kd, int Nn, int Ma, size_t aBatch, size_t bBatch, size_t cBatch) {
    extern __shared__ __align__(16) char gsm[];
    float* As = (float*)gsm;                            // [STAGES][8][128]
    float* Bs = (float*)(gsm + STAGES * 4096);          // [STAGES][8][128]
    unsigned long long* skey = (unsigned long long*)(gsm + 2 * STAGES * 4096);
    float* colsum = (float*)(gsm + 2 * STAGES * 4096 + 1024);

    int b = blockIdx.z;
    const float* ATb = AT + (size_t)b * aBatch;
    const float* Bb = B + (size_t)b * bBatch;
    int m0 = blockIdx.x * 128;
    int tid = threadIdx.x;
    int tx = tid & 15, ty = tid >> 4;
    int lkk = tid >> 4, lc = (tid & 15) * 4;  // loader: row kk, float offset

    unsigned sAb = (unsigned)__cvta_generic_to_shared(As) + lkk * 512 + lc * 4;
    unsigned sBb = (unsigned)__cvta_generic_to_shared(Bs) + lkk * 512 + lc * 4;

    if (MODE == 0) skey[tid] = 0xFFFFFFFFFFFFFFFFull;

    int nk = Kd >> 3;
    int ntiles = Nn >> 7;
    for (int nt = 0; nt < ntiles; nt++) {
        int n0 = nt << 7;
        unsigned long long acc[8][8];
#pragma unroll
        for (int i = 0; i < 8; i++)
#pragma unroll
            for (int j = 0; j < 8; j++) acc[i][j] = 0ull;

        auto issue = [&](int t, int st) {
            int krow = (t << 3) + lkk;
            const float* ga = ATb + (size_t)krow * Ma + m0 + lc;
            const float* gb = Bb + (size_t)krow * Nn + n0 + lc;
            unsigned sa = sAb + st * 4096;
            unsigned sb = sBb + st * 4096;
            asm volatile(
                "cp.async.cg.shared.global [%0], [%1], 16;\n\t"
                "cp.async.cg.shared.global [%2], [%3], 16;\n\t"
                "cp.async.cg.shared.global [%4], [%5], 16;\n\t"
                "cp.async.cg.shared.global [%6], [%7], 16;\n\t"
                "cp.async.commit_group;\n\t" ::
                "r"(sa), "l"(ga), "r"(sa + 256), "l"(ga + 64),
                "r"(sb), "l"(gb), "r"(sb + 256), "l"(gb + 64));
        };

        for (int p = 0; p < STAGES - 1; p++) issue(p, p);

        for (int t = 0; t < nk; t++) {
            asm volatile("cp.async.wait_group %0;" :: "n"(STAGES - 2));
            __syncthreads();
            if (t + STAGES - 1 < nk) issue(t + STAGES - 1, (t + STAGES - 1) & (STAGES - 1));
            else asm volatile("cp.async.commit_group;");  // keep group count uniform
            int st = t & (STAGES - 1);
            const float* Ast = As + st * 1024;
            const float* Bst = Bs + st * 1024;
#pragma unroll
            for (int kk = 0; kk < 8; kk++) {
                const ulonglong2* apv = (const ulonglong2*)(Ast + kk * 128 + ty * 16);
                ulonglong2 A0 = apv[0], A1 = apv[1], A2 = apv[2], A3 = apv[3];
                uint4 b0 = *(const uint4*)(Bst + kk * 128 + tx * 8);
                uint4 b1 = *(const uint4*)(Bst + kk * 128 + tx * 8 + 4);
                unsigned long long ap[8] = {A0.x, A0.y, A1.x, A1.y,
                                            A2.x, A2.y, A3.x, A3.y};
                unsigned long long bd[8] = {dup2(b0.x), dup2(b0.y), dup2(b0.z),
                                            dup2(b0.w), dup2(b1.x), dup2(b1.y),
                                            dup2(b1.z), dup2(b1.w)};
#pragma unroll
                for (int i = 0; i < 8; i++)
#pragma unroll
                    for (int j = 0; j < 8; j++) ffma2(acc[i][j], ap[i], bd[j]);
            }
        }
        __syncthreads();  // all warps done with smem buffers before epilogue/next tile

        if (MODE == 0) {
            float c2v[8];
#pragma unroll
            for (int j = 0; j < 8; j++) c2v[j] = g_c2[b * KC + n0 + tx * 8 + j];
            float x2v[16];
#pragma unroll
            for (int i = 0; i < 16; i++)
                x2v[i] = g_x2[b * NPTS + m0 + ty * 16 + i];
#pragma unroll
            for (int mp = 0; mp < 8; mp++) {
#pragma unroll
                for (int h = 0; h < 2; h++) {
                    int rl = ty * 16 + 2 * mp + h;
                    unsigned long long best = 0xFFFFFFFFFFFFFFFFull;
#pragma unroll
                    for (int j = 0; j < 8; j++) {
                        float dot = ((const float*)&acc[mp][j])[h];
                        float d = (x2v[2 * mp + h] + c2v[j]) - 2.0f * dot;
                        unsigned u = __float_as_uint(d);
                        u = (u & 0x80000000u) ? ~u : (u | 0x80000000u);
                        unsigned long long key =
                            ((unsigned long long)u << 32) |
                            (unsigned)(n0 + tx * 8 + j);
                        best = (key < best) ? key : best;
                    }
                    atomicMin(&skey[rl], best);
                }
            }
        } else if (MODE == 1) {
            float* Cb = C + (size_t)b * cBatch;
#pragma unroll
            for (int mp = 0; mp < 8; mp++) {
#pragma unroll
                for (int h = 0; h < 2; h++) {
                    float* p = Cb + (size_t)(m0 + ty * 16 + 2 * mp + h) * Nn +
                               n0 + tx * 8;
                    float4 v0, v1;
#pragma unroll
                    for (int j = 0; j < 4; j++) {
                        (&v0.x)[j] = ((const float*)&acc[mp][j])[h];
                        (&v1.x)[j] = ((const float*)&acc[mp][j + 4])[h];
                    }
                    *(float4*)p = v0;
                    *(float4*)(p + 4) = v1;
                }
            }
        } else {
            colsum[tid] = 0.f;
            float bj[8];
#pragma unroll
            for (int j = 0; j < 8; j++) bj[j] = bias[n0 + tx * 8 + j];
            __syncthreads();
            float part[8] = {0, 0, 0, 0, 0, 0, 0, 0};
#pragma unroll
            for (int mp = 0; mp < 8; mp++)
#pragma unroll
                for (int j = 0; j < 8; j++) {
                    part[j] += mishf(((const float*)&acc[mp][j])[0] + bj[j]);
                    part[j] += mishf(((const float*)&acc[mp][j])[1] + bj[j]);
                }
#pragma unroll
            for (int j = 0; j < 8; j++) atomicAdd(&colsum[tx * 8 + j], part[j]);
            __syncthreads();
            atomicAdd(&g_pooled[b * DIM + n0 + tid], colsum[tid]);
        }
        __syncthreads();
    }

    if (MODE == 0)
        g_labels[b * NPTS + m0 + tid] = (int)(skey[tid] & 0xFFFFFFFFu);
}

// ---------------- parallel stable member-list build + chunk slots -----------
// 512 threads, 16 chunks of 256; u16 labels keep static smem at 47KB.
__global__ __launch_bounds__(512) void listbuild_kernel() {
    __shared__ unsigned short labs[NPTS];  // 8KB
    __shared__ int cnt[16][KC];            // 32KB: counts -> chunk cursors
    __shared__ int tot[KC];
    __shared__ int offs[KC];
    __shared__ int schoff[KC];
    int b = blockIdx.x, t = threadIdx.x;
    int w = t >> 5, lane = t & 31;

    for (int idx = t; idx < 16 * KC; idx += 512) ((int*)cnt)[idx] = 0;
    for (int i = t; i < NPTS; i += 512)
        labs[i] = (unsigned short)g_labels[b * NPTS + i];
    __syncthreads();

    // warp w histograms chunk w (256 elems): 8 rounds
    for (int r = 0; r < 8; r++) {
        int i = w * 256 + r * 32 + lane;
        atomicAdd(&cnt[w][labs[i]], 1);
    }
    __syncthreads();

    // per-label prefix over 16 chunks (one label per thread)
    for (int l = t; l < KC; l += 512) {
        int s = 0;
#pragma unroll
        for (int ch = 0; ch < 16; ch++) {
            int c = cnt[ch][l];
            cnt[ch][l] = s;
            s += c;
        }
        tot[l] = s;
    }
    __syncthreads();

    // warp 0: member-count exclusive scan; warp 1: chunk-count scan
    if (t < 32) {
        int carry = 0;
        for (int c = 0; c < KC / 32; c++) {
            int v = tot[c * 32 + t];
            int x = v;
#pragma unroll
            for (int o = 1; o < 32; o <<= 1) {
                int y = __shfl_up_sync(0xffffffffu, x, o);
                if (t >= o) x += y;
            }
            offs[c * 32 + t] = carry + x - v;
            carry += __shfl_sync(0xffffffffu, x, 31);
        }
    } else if (t < 64) {
        int tl = t - 32;
        int carry = 0;
        for (int c = 0; c < KC / 32; c++) {
            int v = (tot[c * 32 + tl] + 15) >> 4;
            int x = v;
#pragma unroll
            for (int o = 1; o < 32; o <<= 1) {
                int y = __shfl_up_sync(0xffffffffu, x, o);
                if (tl >= o) x += y;
            }
            schoff[c * 32 + tl] = carry + x - v;
            carry += __shfl_sync(0xffffffffu, x, 31);
        }
        if (tl == 31) g_nslots[b] = carry;
    }
    __syncthreads();
    for (int l = t; l < KC; l += 512) {
        g_counts[b * KC + l] = tot[l];
        g_offs[b * KC + l] = offs[l];
        g_choff[b * KC + l] = schoff[l];
        int nc = (tot[l] + 15) >> 4;
        int base = schoff[l];
        for (int j = 0; j < nc; j++) {
            g_slot_s[b * NSLOT + base + j] = offs[l] + j * 16;
            g_slot_n[b * NSLOT + base + j] = min(16, tot[l] - j * 16);
        }
    }
    for (int idx = t; idx < 16 * KC; idx += 512) {
        int ch = idx >> 9, l = idx & (KC - 1);
        cnt[ch][l] += offs[l];
    }
    __syncthreads();

    // stable scatter: warp w handles chunk w, 8 sequential rounds
    unsigned below = (lane == 0) ? 0u : (0xffffffffu >> (32 - lane));
    for (int r = 0; r < 8; r++) {
        int i = w * 256 + r * 32 + lane;
        int l = labs[i];
        unsigned mask = __match_any_sync(0xffffffffu, l);
        int base = cnt[w][l];
        __syncwarp();
        int rank = __popc(mask & below);
        g_list[b * NPTS + base + rank] = i;
        if (lane == __ffs(mask) - 1) cnt[w][l] = base + __popc(mask);
        __syncwarp();
    }
}

// ---------------- center update pass 1: sum each 16-member chunk ------------
__global__ __launch_bounds__(128) void gather_pass1_kernel(const float* __restrict__ X) {
    int b = blockIdx.y, slot = blockIdx.x, t = threadIdx.x;
    if (slot >= g_nslots[b]) return;
    int s = g_slot_s[b * NSLOT + slot];
    int n = g_slot_n[b * NSLOT + slot];
    const int* lst = g_list + b * NPTS + s;
    const float* Xb = X + (size_t)b * NPTS * DIM;
    float4 a = {0, 0, 0, 0};
    for (int e = 0; e < n; e++) {
        float4 v = *(const float4*)(Xb + (size_t)lst[e] * DIM + t * 4);
        a.x += v.x; a.y += v.y; a.z += v.z; a.w += v.w;
    }
    *(float4*)(g_partial + ((size_t)b * NSLOT + slot) * DIM + t * 4) = a;
}

// ---------------- center update pass 2: combine chunks, write centersT, c2 --
__global__ __launch_bounds__(128) void gather_pass2_kernel() {
    int b = blockIdx.y, k = blockIdx.x, t = threadIdx.x;
    int cnt = g_counts[b * KC + k];
    int c0 = g_choff[b * KC + k];
    int nch = (cnt + 15) >> 4;
    float* cT = g_centersT + (size_t)b * DIM * KC;
    float4 v;
    if (cnt > 0) {
        float4 a = {0, 0, 0, 0};
        for (int c = 0; c < nch; c++) {
            float4 p = *(const float4*)(g_partial + ((size_t)b * NSLOT + c0 + c) * DIM + t * 4);
            a.x += p.x; a.y += p.y; a.z += p.z; a.w += p.w;
        }
        float cf = (float)cnt;
        v = make_float4(a.x / cf, a.y / cf, a.z / cf, a.w / cf);
        cT[(size_t)(t * 4 + 0) * KC + k] = v.x;
        cT[(size_t)(t * 4 + 1) * KC + k] = v.y;
        cT[(size_t)(t * 4 + 2) * KC + k] = v.z;
        cT[(size_t)(t * 4 + 3) * KC + k] = v.w;
    } else {
        v.x = cT[(size_t)(t * 4 + 0) * KC + k];
        v.y = cT[(size_t)(t * 4 + 1) * KC + k];
        v.z = cT[(size_t)(t * 4 + 2) * KC + k];
        v.w = cT[(size_t)(t * 4 + 3) * KC + k];
    }
    float sq = v.x * v.x + v.y * v.y + v.z * v.z + v.w * v.w;
    for (int o = 16; o > 0; o >>= 1) sq += __shfl_down_sync(0xffffffffu, sq, o);
    __shared__ float w[4];
    if ((t & 31) == 0) w[t >> 5] = sq;
    __syncthreads();
    if (t == 0) g_c2[b * KC + k] = w[0] + w[1] + w[2] + w[3];
}

// ------- h_next = mish(adj @ one_hot(labels)), 16 rows/block; writes h & hT -
// Atomic phase: each warp owns 2 rows -> contention pool 256 -> 32 threads.
__global__ __launch_bounds__(256) void segsum_mish_kernel(const float* __restrict__ adj,
                                                          float* __restrict__ Hout,
                                                          float* __restrict__ HoutT) {
    int b = blockIdx.y, i0 = blockIdx.x * 16, t = threadIdx.x;  // 256 threads
    int w = t >> 5, lane = t & 31;
    __shared__ float acc[16][KC];            // 32KB
    __shared__ unsigned short labs[NPTS];    // 8KB
    const int* lb = g_labels + b * NPTS;
    for (int j = t; j < NPTS; j += 256) labs[j] = (unsigned short)lb[j];
#pragma unroll
    for (int r = 0; r < 16; r++)
        for (int k = t; k < KC; k += 256) acc[r][k] = 0.f;
    __syncthreads();
#pragma unroll
    for (int rr = 0; rr < 2; rr++) {
        int r = w * 2 + rr;
        const float* arow = adj + ((size_t)b * NPTS + i0 + r) * NPTS;
        for (int j = lane; j < NPTS; j += 32) atomicAdd(&acc[r][labs[j]], arow[j]);
    }
    __syncthreads();
    for (int k = t; k < KC; k += 256) {
        float tmp[16];
#pragma unroll
        for (int r = 0; r < 16; r++) tmp[r] = mishf(acc[r][k]);
#pragma unroll
        for (int r = 0; r < 16; r++)
            Hout[((size_t)b * NPTS + i0 + r) * DIM + k] = tmp[r];
        float4* dstT = (float4*)(HoutT + ((size_t)b * DIM + k) * NPTS + i0);
#pragma unroll
        for (int q = 0; q < 4; q++)
            dstT[q] = make_float4(tmp[q * 4], tmp[q * 4 + 1], tmp[q * 4 + 2], tmp[q * 4 + 3]);
    }
}

__global__ void zero_pooled_kernel() {
    g_pooled[blockIdx.x * DIM + threadIdx.x] = 0.f;
}

// ---------------- out = pooled @ Wp + bp ----------------
__global__ void out_kernel(const float* __restrict__ Wp, const float* __restrict__ bp,
                           float* __restrict__ out) {
    int b = blockIdx.x, t = threadIdx.x;  // 32 threads
    if (t < OUTD) {
        const float* p = g_pooled + b * DIM;
        float s = 0.f;
        for (int h = 0; h < DIM; h++) s += p[h] * Wp[h * OUTD + t];
        out[b * OUTD + t] = s + bp[t];
    }
}

// ---------------- host orchestration ----------------
static void run_ctod(const float* X, const float* XT, const float* centersT) {
    rowsq_kernel<<<dim3(NPTS, BATCH), 128>>>(X);   // also seeds g_c2 (rows < KC)
    initcT_kernel<<<dim3(DIM, BATCH), 128>>>(XT);
    for (int it = 0; it < 10; it++) {
        gemm_kernel<0><<<dim3(NPTS / 128, 1, BATCH), 128, GEMM_SMEM>>>(
            XT, centersT, nullptr, nullptr, DIM, KC, NPTS,
            (size_t)DIM * NPTS, (size_t)DIM * KC, (size_t)0);
        if (it < 9) {
            listbuild_kernel<<<BATCH, 512>>>();
            gather_pass1_kernel<<<dim3(NSLOT, BATCH), 128>>>(X);
            gather_pass2_kernel<<<dim3(KC, BATCH), 128>>>();
        }
    }
}

extern "C" void kernel_launch(void* const* d_in, const int* in_sizes, int n_in,
                              void* d_out, int out_size) {
    const float* x   = (const float*)d_in[0];
    const float* adj = (const float*)d_in[1];
    const float* W   = (const float*)d_in[2];
    const float* bb  = (const float*)d_in[3];
    const float* Wp  = (const float*)d_in[4];
    const float* bp  = (const float*)d_in[5];
    float* out = (float*)d_out;

    cudaFuncSetAttribute(gemm_kernel<0>,
                         cudaFuncAttributeMaxDynamicSharedMemorySize, GEMM_SMEM);
    cudaFuncSetAttribute(gemm_kernel<1>,
                         cudaFuncAttributeMaxDynamicSharedMemorySize, GEMM_SMEM);
    cudaFuncSetAttribute(gemm_kernel<2>,
                         cudaFuncAttributeMaxDynamicSharedMemorySize, GEMM_SMEM);

    float *h0, *h1, *hT, *adjT, *centersT;
    cudaGetSymbolAddress((void**)&h0, g_buf0);
    cudaGetSymbolAddress((void**)&h1, g_buf1);
    cudaGetSymbolAddress((void**)&hT, g_bufT);
    cudaGetSymbolAddress((void**)&adjT, g_adjT);
    cudaGetSymbolAddress((void**)&centersT, g_centersT);

    // one-time transposes
    transpose_kernel<<<dim3(DIM / 32, NPTS / 32, BATCH), dim3(32, 8)>>>(x, hT, NPTS, DIM);
    transpose_kernel<<<dim3(NPTS / 32, NPTS / 32, BATCH), dim3(32, 8)>>>(adj, adjT, NPTS, NPTS);

    // Layer 1: ctod(x) -> segsum -> h0 (+ h0T in hT)
    run_ctod(x, hT, centersT);
    segsum_mish_kernel<<<dim3(NPTS / 16, BATCH), 256>>>(adj, h0, hT);
    // Layer 2
    run_ctod(h0, hT, centersT);
    segsum_mish_kernel<<<dim3(NPTS / 16, BATCH), 256>>>(adj, h1, hT);
    // Layer 3
    run_ctod(h1, hT, centersT);
    segsum_mish_kernel<<<dim3(NPTS / 16, BATCH), 256>>>(adj, h0, hT);

    // Final layer: t = h0 @ W (A = h0T in hT), then pooled mish(adj @ t + b)
    gemm_kernel<1><<<dim3(NPTS / 128, 1, BATCH), 128, GEMM_SMEM>>>(
        hT, W, h1, nullptr, DIM, DIM, NPTS,
        (size_t)DIM * NPTS, (size_t)0, (size_t)NPTS * DIM);
    zero_pooled_kernel<<<BATCH, DIM>>>();
    gemm_kernel<2><<<dim3(NPTS / 128, 1, BATCH), 128, GEMM_SMEM>>>(
        adjT, h1, nullptr, bb, NPTS, DIM, NPTS,
        (size_t)NPTS * NPTS, (size_t)NPTS * DIM, (size_t)0);
    out_kernel<<<BATCH, 32>>>(Wp, bp, out);
}